// round 2
// baseline (speedup 1.0000x reference)
#include <cuda_runtime.h>
#include <math.h>

#define BATCH 131072

__device__ float g_H[(size_t)BATCH * 256];
__device__ float g_raw[BATCH];
__device__ float g_part[256];
__device__ float g_scalars[2];

// ================= K1: H = relu(contact @ W1^T + b1) =================
__global__ __launch_bounds__(256) void k1_gemm(const float* __restrict__ obs,
                                               const float* __restrict__ W1,
                                               const float* __restrict__ b1) {
    __shared__ float As[8 * 64];
    __shared__ float Ws[8 * 256];
    const int tid = threadIdx.x;
    const int tx = tid & 31, ty = tid >> 5;
    const int row0 = blockIdx.x * 64;

    float acc[8][8];
#pragma unroll
    for (int i = 0; i < 8; ++i)
#pragma unroll
        for (int j = 0; j < 8; ++j) acc[i][j] = 0.f;

    float pA[2], pW[8];
#pragma unroll
    for (int l = 0; l < 2; ++l) {
        int idx = tid + l * 256;
        int r = idx >> 3, kk = idx & 7;
        int col = (kk < 224) ? (45 + kk) : (68 + kk);
        pA[l] = obs[(size_t)(row0 + r) * 376 + col];
    }
#pragma unroll
    for (int kk = 0; kk < 8; ++kk) pW[kk] = W1[(size_t)tid * 308 + kk];

    for (int kt = 0; kt < 39; ++kt) {
        __syncthreads();
#pragma unroll
        for (int l = 0; l < 2; ++l) {
            int idx = tid + l * 256;
            As[(idx & 7) * 64 + (idx >> 3)] = pA[l];
        }
#pragma unroll
        for (int kk = 0; kk < 8; ++kk) Ws[kk * 256 + tid] = pW[kk];
        __syncthreads();

        if (kt < 38) {
            int kb = (kt + 1) * 8;
#pragma unroll
            for (int l = 0; l < 2; ++l) {
                int idx = tid + l * 256;
                int r = idx >> 3, k = kb + (idx & 7);
                float v = 0.f;
                if (k < 308) {
                    int col = (k < 224) ? (45 + k) : (68 + k);
                    v = obs[(size_t)(row0 + r) * 376 + col];
                }
                pA[l] = v;
            }
#pragma unroll
            for (int kk = 0; kk < 8; ++kk) {
                int k = kb + kk;
                pW[kk] = (k < 308) ? W1[(size_t)tid * 308 + k] : 0.f;
            }
        }
#pragma unroll
        for (int kk = 0; kk < 8; ++kk) {
            float a[8], bv[8];
#pragma unroll
            for (int i = 0; i < 8; ++i) a[i] = As[kk * 64 + ty + 8 * i];
#pragma unroll
            for (int j = 0; j < 8; ++j) bv[j] = Ws[kk * 256 + tx + 32 * j];
#pragma unroll
            for (int i = 0; i < 8; ++i)
#pragma unroll
                for (int j = 0; j < 8; ++j) acc[i][j] = fmaf(a[i], bv[j], acc[i][j]);
        }
    }
#pragma unroll
    for (int i = 0; i < 8; ++i) {
        int row = row0 + ty + 8 * i;
#pragma unroll
        for (int j = 0; j < 8; ++j) {
            int c = tx + 32 * j;
            g_H[(size_t)row * 256 + c] = fmaxf(acc[i][j] + b1[c], 0.f);
        }
    }
}

// ================= K2: fused tok GEMM + attention + LN + head =================
#define K2_SMEM_FLOATS 45632
#define K2_SMEM_BYTES (K2_SMEM_FLOATS * 4)

__global__ __launch_bounds__(256) void k2_fused(
    const float* __restrict__ obs,
    const float* __restrict__ W2, const float* __restrict__ b2,
    const float* __restrict__ Wr, const float* __restrict__ br,
    const float* __restrict__ Win, const float* __restrict__ bin_,
    const float* __restrict__ Wout, const float* __restrict__ bout,
    const float* __restrict__ gamma, const float* __restrict__ beta,
    const float* __restrict__ Wh1, const float* __restrict__ bh1,
    const float* __restrict__ Wh2, const float* __restrict__ bh2,
    float* __restrict__ out_ctx, float* __restrict__ out_ent) {
    extern __shared__ float sm[];
    float* Hs    = sm;              // 8192
    float* toks  = Hs + 8192;       // 32*520 = 16640
    float* qwS   = toks + 16640;    // 32*260 = 8320
    float* wbuf  = qwS + 8320;      // 4160
    float* rembS = wbuf + 4160;     // 2048
    float* qS    = rembS + 2048;    // 2048
    float* ctxS  = qS + 2048;       // 2048
    float* attnS = ctxS + 2048;     // 1024
    float* rootS = attnS + 1024;    // 384
    float* WrS   = rootS + 384;     // 768

    const int tid = threadIdx.x;
    const int lane = tid & 31, w = tid >> 5;
    const int row0 = blockIdx.x * 32;

    for (int idx = tid; idx < 8192; idx += 256)
        Hs[idx] = g_H[(size_t)row0 * 256 + idx];
    for (int idx = tid; idx < 32 * 11; idx += 256) {
        int r = idx / 11, j = idx % 11;
        int col = (j < 5) ? j : (17 + j);
        rootS[r * 12 + j] = obs[(size_t)(row0 + r) * 376 + col];
    }
    for (int idx = tid; idx < 64 * 11; idx += 256)
        WrS[(idx / 11) * 12 + (idx % 11)] = Wr[idx];
    for (int idx = tid; idx < 4096; idx += 256)   // Wq
        wbuf[(idx >> 6) * 65 + (idx & 63)] = Win[idx];
    __syncthreads();

    // r_emb
#pragma unroll
    for (int rr = 0; rr < 4; ++rr) {
        int r = w * 4 + rr;
#pragma unroll
        for (int half = 0; half < 2; ++half) {
            int e = lane + 32 * half;
            float acc = br[e];
#pragma unroll
            for (int j = 0; j < 11; ++j) acc = fmaf(rootS[r * 12 + j], WrS[e * 12 + j], acc);
            rembS[r * 64 + e] = acc;
        }
    }
    __syncwarp();
    // q = r_emb @ Wq^T + bq
#pragma unroll
    for (int rr = 0; rr < 4; ++rr) {
        int r = w * 4 + rr;
#pragma unroll
        for (int half = 0; half < 2; ++half) {
            int e = lane + 32 * half;
            float acc = bin_[e];
#pragma unroll 8
            for (int d = 0; d < 64; ++d) acc = fmaf(rembS[r * 64 + d], wbuf[e * 65 + d], acc);
            qS[r * 64 + e] = acc;
        }
    }

    // tok GEMM (32 x 512, K=256)
    const int tx2 = tid & 63, ty2 = tid >> 6;
    float acc2[8][8];
#pragma unroll
    for (int i = 0; i < 8; ++i)
#pragma unroll
        for (int j = 0; j < 8; ++j) acc2[i][j] = 0.f;

    float pf[16];
#pragma unroll
    for (int l = 0; l < 2; ++l) {
        int c = tid + l * 256;
#pragma unroll
        for (int kk = 0; kk < 8; ++kk) pf[l * 8 + kk] = W2[(size_t)c * 256 + kk];
    }
    for (int kt = 0; kt < 32; ++kt) {
        __syncthreads();
#pragma unroll
        for (int l = 0; l < 2; ++l) {
            int c = tid + l * 256;
#pragma unroll
            for (int kk = 0; kk < 8; ++kk) wbuf[kk * 512 + c] = pf[l * 8 + kk];
        }
        __syncthreads();
        if (kt < 31) {
            int kb = (kt + 1) * 8;
#pragma unroll
            for (int l = 0; l < 2; ++l) {
                int c = tid + l * 256;
#pragma unroll
                for (int kk = 0; kk < 8; ++kk) pf[l * 8 + kk] = W2[(size_t)c * 256 + kb + kk];
            }
        }
        int kbase = kt * 8;
#pragma unroll
        for (int kk = 0; kk < 8; ++kk) {
            float a[8], bv[8];
#pragma unroll
            for (int i = 0; i < 8; ++i) a[i] = Hs[(ty2 + 4 * i) * 256 + kbase + kk];
#pragma unroll
            for (int j = 0; j < 8; ++j) bv[j] = wbuf[kk * 512 + tx2 + 64 * j];
#pragma unroll
            for (int i = 0; i < 8; ++i)
#pragma unroll
                for (int j = 0; j < 8; ++j) acc2[i][j] = fmaf(a[i], bv[j], acc2[i][j]);
        }
    }
    __syncthreads();
#pragma unroll
    for (int i = 0; i < 8; ++i) {
        int r = ty2 + 4 * i;
#pragma unroll
        for (int j = 0; j < 8; ++j) {
            int c = tx2 + 64 * j;
            toks[r * 520 + (c >> 6) * 65 + (c & 63)] = acc2[i][j] + b2[c];
        }
    }
    for (int idx = tid; idx < 4096; idx += 256)   // Wk
        wbuf[(idx >> 6) * 65 + (idx & 63)] = Win[4096 + idx];
    __syncthreads();

    // per-row: fold q into Wk, scores, softmax, entropy, wtok
    {
        const int h = lane >> 3, t = lane & 7;
#pragma unroll
        for (int rr = 0; rr < 4; ++rr) {
            int r = w * 4 + rr;
            size_t row = (size_t)row0 + r;
#pragma unroll
            for (int hh = 0; hh < 4; ++hh)
#pragma unroll
                for (int half = 0; half < 2; ++half) {
                    int j = lane + 32 * half;
                    float acc = 0.f;
#pragma unroll
                    for (int e = 0; e < 16; ++e)
                        acc = fmaf(qS[r * 64 + hh * 16 + e], wbuf[(hh * 16 + e) * 65 + j], acc);
                    qwS[r * 260 + hh * 65 + j] = acc * 0.25f;
                }
            __syncwarp();
            float qbk = 0.f;
#pragma unroll
            for (int e = 0; e < 16; ++e)
                qbk = fmaf(qS[r * 64 + h * 16 + e], bin_[64 + h * 16 + e], qbk);
            float s = qbk * 0.25f;
#pragma unroll 8
            for (int j = 0; j < 64; ++j)
                s = fmaf(toks[r * 520 + t * 65 + j], qwS[r * 260 + h * 65 + j], s);
            float m = s;
            m = fmaxf(m, __shfl_xor_sync(0xffffffffu, m, 1, 8));
            m = fmaxf(m, __shfl_xor_sync(0xffffffffu, m, 2, 8));
            m = fmaxf(m, __shfl_xor_sync(0xffffffffu, m, 4, 8));
            float ex = expf(s - m);
            float den = ex;
            den += __shfl_xor_sync(0xffffffffu, den, 1, 8);
            den += __shfl_xor_sync(0xffffffffu, den, 2, 8);
            den += __shfl_xor_sync(0xffffffffu, den, 4, 8);
            float a = ex / den;
            attnS[r * 32 + lane] = a;
            float ah = a;
            ah += __shfl_xor_sync(0xffffffffu, ah, 8);
            ah += __shfl_xor_sync(0xffffffffu, ah, 16);
            float aw = fmaxf(ah * 0.25f, 1e-8f);
            float term = -aw * logf(aw);
            term += __shfl_xor_sync(0xffffffffu, term, 1, 8);
            term += __shfl_xor_sync(0xffffffffu, term, 2, 8);
            term += __shfl_xor_sync(0xffffffffu, term, 4, 8);
            if (lane == 0) out_ent[row] = term;
            __syncwarp();
#pragma unroll
            for (int hh = 0; hh < 4; ++hh)
#pragma unroll
                for (int half = 0; half < 2; ++half) {
                    int j = lane + 32 * half;
                    float acc = 0.f;
#pragma unroll
                    for (int tt = 0; tt < 8; ++tt)
                        acc = fmaf(attnS[r * 32 + hh * 8 + tt], toks[r * 520 + tt * 65 + j], acc);
                    qwS[r * 260 + hh * 65 + j] = acc;
                }
            __syncwarp();
        }
    }
    __syncthreads();
    for (int idx = tid; idx < 4096; idx += 256)   // Wv
        wbuf[(idx >> 6) * 65 + (idx & 63)] = Win[8192 + idx];
    __syncthreads();

    // ctx
#pragma unroll
    for (int rr = 0; rr < 4; ++rr) {
        int r = w * 4 + rr;
#pragma unroll
        for (int half = 0; half < 2; ++half) {
            int d = lane + 32 * half;
            int h = d >> 4;
            float acc = bin_[128 + d];
#pragma unroll 8
            for (int j = 0; j < 64; ++j)
                acc = fmaf(qwS[r * 260 + h * 65 + j], wbuf[d * 65 + j], acc);
            ctxS[r * 64 + d] = acc;
        }
    }
    __syncthreads();
    for (int idx = tid; idx < 4096; idx += 256)   // Wout
        wbuf[(idx >> 6) * 65 + (idx & 63)] = Wout[idx];
    __syncthreads();

    // attn_out + residual + LayerNorm
#pragma unroll
    for (int rr = 0; rr < 4; ++rr) {
        int r = w * 4 + rr;
        size_t row = (size_t)row0 + r;
        float x0, x1;
        {
            float acc = bout[lane];
#pragma unroll 8
            for (int d = 0; d < 64; ++d) acc = fmaf(ctxS[r * 64 + d], wbuf[lane * 65 + d], acc);
            x0 = acc + rembS[r * 64 + lane];
        }
        {
            int e = lane + 32;
            float acc = bout[e];
#pragma unroll 8
            for (int d = 0; d < 64; ++d) acc = fmaf(ctxS[r * 64 + d], wbuf[e * 65 + d], acc);
            x1 = acc + rembS[r * 64 + e];
        }
        float ssum = x0 + x1;
#pragma unroll
        for (int o = 16; o > 0; o >>= 1) ssum += __shfl_xor_sync(0xffffffffu, ssum, o);
        float mu = ssum * (1.f / 64.f);
        float d0 = x0 - mu, d1 = x1 - mu;
        float vs = d0 * d0 + d1 * d1;
#pragma unroll
        for (int o = 16; o > 0; o >>= 1) vs += __shfl_xor_sync(0xffffffffu, vs, o);
        float inv = rsqrtf(vs * (1.f / 64.f) + 1e-5f);
        float c0 = fmaf(gamma[lane], d0 * inv, beta[lane]);
        float c1 = fmaf(gamma[lane + 32], d1 * inv, beta[lane + 32]);
        out_ctx[row * 64 + lane] = c0;
        out_ctx[row * 64 + lane + 32] = c1;
        __syncwarp();
        ctxS[r * 64 + lane] = c0;
        ctxS[r * 64 + lane + 32] = c1;
        __syncwarp();
    }
    __syncthreads();
    for (int idx = tid; idx < 2048; idx += 256)   // Wh1
        wbuf[(idx >> 6) * 65 + (idx & 63)] = Wh1[idx];
    __syncthreads();

    // head MLP -> raw
#pragma unroll
    for (int rr = 0; rr < 4; ++rr) {
        int r = w * 4 + rr;
        size_t row = (size_t)row0 + r;
        float acc = bh1[lane];
#pragma unroll 8
        for (int d = 0; d < 64; ++d) acc = fmaf(ctxS[r * 64 + d], wbuf[lane * 65 + d], acc);
        float v = fmaxf(acc, 0.f) * Wh2[lane];
#pragma unroll
        for (int o = 16; o > 0; o >>= 1) v += __shfl_xor_sync(0xffffffffu, v, o);
        if (lane == 0) g_raw[row] = v + bh2[0];
    }
}

// ================= batch reductions =================
__global__ void k_reduce_raw() {
    __shared__ float s[256];
    int tid = threadIdx.x;
    int i = blockIdx.x * 512 + tid;
    s[tid] = g_raw[i] + g_raw[i + 256];
    __syncthreads();
    for (int o = 128; o > 0; o >>= 1) {
        if (tid < o) s[tid] += s[tid + o];
        __syncthreads();
    }
    if (tid == 0) g_part[blockIdx.x] = s[0];
}
__global__ void k_finish_raw() {
    __shared__ float s[256];
    int tid = threadIdx.x;
    s[tid] = g_part[tid];
    __syncthreads();
    for (int o = 128; o > 0; o >>= 1) {
        if (tid < o) s[tid] += s[tid + o];
        __syncthreads();
    }
    if (tid == 0) g_scalars[0] = s[0] * (1.f / (float)BATCH);
}
__global__ void k_reduce_lw() {
    __shared__ float s[256];
    int tid = threadIdx.x;
    float mean = g_scalars[0];
    int i = blockIdx.x * 512 + tid;
    s[tid] = expf(0.5f * tanhf(g_raw[i] - mean)) +
             expf(0.5f * tanhf(g_raw[i + 256] - mean));
    __syncthreads();
    for (int o = 128; o > 0; o >>= 1) {
        if (tid < o) s[tid] += s[tid + o];
        __syncthreads();
    }
    if (tid == 0) g_part[blockIdx.x] = s[0];
}
__global__ void k_finish_lw() {
    __shared__ float s[256];
    int tid = threadIdx.x;
    s[tid] = g_part[tid];
    __syncthreads();
    for (int o = 128; o > 0; o >>= 1) {
        if (tid < o) s[tid] += s[tid + o];
        __syncthreads();
    }
    if (tid == 0) g_scalars[1] = fmaxf(s[0] * (1.f / (float)BATCH), 1e-6f);
}
__global__ void k_write_lw(float* __restrict__ out_lw) {
    int i = blockIdx.x * 256 + threadIdx.x;
    float lw = expf(0.5f * tanhf(g_raw[i] - g_scalars[0]));
    out_lw[i] = lw / g_scalars[1];
}

// =====================================================================
extern "C" void kernel_launch(void* const* d_in, const int* in_sizes, int n_in,
                              void* d_out, int out_size) {
    const float* obs   = (const float*)d_in[0];
    const float* W1    = (const float*)d_in[1];
    const float* b1    = (const float*)d_in[2];
    const float* W2    = (const float*)d_in[3];
    const float* b2    = (const float*)d_in[4];
    const float* Wr    = (const float*)d_in[5];
    const float* br    = (const float*)d_in[6];
    const float* Win   = (const float*)d_in[7];
    const float* bin_  = (const float*)d_in[8];
    const float* Wout  = (const float*)d_in[9];
    const float* bout  = (const float*)d_in[10];
    const float* gamma = (const float*)d_in[11];
    const float* beta  = (const float*)d_in[12];
    const float* Wh1   = (const float*)d_in[13];
    const float* bh1   = (const float*)d_in[14];
    const float* Wh2   = (const float*)d_in[15];
    const float* bh2   = (const float*)d_in[16];

    float* out     = (float*)d_out;
    float* out_ctx = out;
    float* out_lw  = out + (size_t)BATCH * 64;
    float* out_ent = out_lw + BATCH;

    cudaFuncSetAttribute(k2_fused, cudaFuncAttributeMaxDynamicSharedMemorySize,
                         K2_SMEM_BYTES);

    k1_gemm<<<BATCH / 64, 256>>>(obs, W1, b1);
    k2_fused<<<BATCH / 32, 256, K2_SMEM_BYTES>>>(
        obs, W2, b2, Wr, br, Win, bin_, Wout, bout, gamma, beta,
        Wh1, bh1, Wh2, bh2, out_ctx, out_ent);
    k_reduce_raw<<<256, 256>>>();
    k_finish_raw<<<1, 256>>>();
    k_reduce_lw<<<256, 256>>>();
    k_finish_lw<<<1, 256>>>();
    k_write_lw<<<BATCH / 256, 256>>>(out_lw);
}

// round 3
// speedup vs baseline: 3.0647x; 3.0647x over previous
#include <cuda_runtime.h>
#include <math.h>

#define BATCH 131072

__device__ float g_H[(size_t)BATCH * 256];
__device__ float g_tok[(size_t)BATCH * 512];
__device__ float g_raw[BATCH];
__device__ float g_part[256];
__device__ float g_scalars[2];

// ---------------- tf32 helpers ----------------
__device__ __forceinline__ unsigned cvt_tf32(float x) {
    unsigned u;
    asm("cvt.rna.tf32.f32 %0, %1;" : "=r"(u) : "f"(x));
    return u;
}
__device__ __forceinline__ void cp4(unsigned dst, const float* src, unsigned sz) {
    asm volatile("cp.async.ca.shared.global [%0], [%1], 4, %2;" ::
                 "r"(dst), "l"(src), "r"(sz));
}
__device__ __forceinline__ void cp16(unsigned dst, const float* src) {
    asm volatile("cp.async.cg.shared.global [%0], [%1], 16;" ::
                 "r"(dst), "l"(src));
}
#define CP_COMMIT asm volatile("cp.async.commit_group;")
#define CP_WAIT0  asm volatile("cp.async.wait_group 0;")

__device__ __forceinline__ void mma8(float* d, const unsigned* a, const unsigned* b) {
    asm volatile(
        "mma.sync.aligned.m16n8k8.row.col.f32.tf32.tf32.f32 "
        "{%0,%1,%2,%3}, {%4,%5,%6,%7}, {%8,%9}, {%0,%1,%2,%3};"
        : "+f"(d[0]), "+f"(d[1]), "+f"(d[2]), "+f"(d[3])
        : "r"(a[0]), "r"(a[1]), "r"(a[2]), "r"(a[3]), "r"(b[0]), "r"(b[1]));
}

// ============ tf32 tile GEMM: C[M x N] = act(A[M x K] @ W[N x K]^T + bias) ============
// 128x128 tile, 256 threads (8 warps as 2m x 4n, warp tile 64x32), BK=16, 2-stage cp.async
template <int KT, bool GATHER, bool RELU, int LDA, int KROW, int LDC>
__global__ __launch_bounds__(256) void gemm_tf32(const float* __restrict__ A,
                                                 const float* __restrict__ W,
                                                 const float* __restrict__ bias,
                                                 float* __restrict__ C) {
    __shared__ float As[2][128][20];
    __shared__ float Bs[2][128][20];
    const int tid = threadIdx.x;
    const int lane = tid & 31, w = tid >> 5;
    const int row0 = blockIdx.x * 128, n0 = blockIdx.y * 128;
    const int wm = (w & 1) * 64, wn = (w >> 1) * 32;
    const int g = lane >> 2, tig = lane & 3;

    float acc[4][4][4] = {};

    auto loadTile = [&](int s, int kt) {
        const int kb = kt * 16;
        if (GATHER) {
#pragma unroll
            for (int l = 0; l < 8; ++l) {
                int idx = tid + l * 256;
                int r = idx >> 4, kk = idx & 15;
                int k = kb + kk;
                int col = (k < 224) ? (45 + k) : (68 + k);
                const float* src = A + (size_t)(row0 + r) * LDA + ((k < KROW) ? col : 0);
                cp4((unsigned)__cvta_generic_to_shared(&As[s][r][kk]), src,
                    (k < KROW) ? 4u : 0u);
            }
#pragma unroll
            for (int l = 0; l < 8; ++l) {
                int idx = tid + l * 256;
                int n = idx >> 4, kk = idx & 15;
                int k = kb + kk;
                const float* src = W + (size_t)(n0 + n) * KROW + ((k < KROW) ? k : 0);
                cp4((unsigned)__cvta_generic_to_shared(&Bs[s][n][kk]), src,
                    (k < KROW) ? 4u : 0u);
            }
        } else {
#pragma unroll
            for (int l = 0; l < 2; ++l) {
                int idx = tid + l * 256;
                int r = idx >> 2, c = (idx & 3) * 4;
                cp16((unsigned)__cvta_generic_to_shared(&As[s][r][c]),
                     A + (size_t)(row0 + r) * KROW + kb + c);
            }
#pragma unroll
            for (int l = 0; l < 2; ++l) {
                int idx = tid + l * 256;
                int n = idx >> 2, c = (idx & 3) * 4;
                cp16((unsigned)__cvta_generic_to_shared(&Bs[s][n][c]),
                     W + (size_t)(n0 + n) * KROW + kb + c);
            }
        }
    };

    loadTile(0, 0);
    CP_COMMIT;

    for (int kt = 0; kt < KT; ++kt) {
        CP_WAIT0;
        __syncthreads();
        if (kt + 1 < KT) {
            loadTile((kt + 1) & 1, kt + 1);
            CP_COMMIT;
        }
        const int s = kt & 1;
#pragma unroll
        for (int km = 0; km < 2; ++km) {
            unsigned a[4][4], b[4][2];
            const int k0 = km * 8 + tig;
#pragma unroll
            for (int mt = 0; mt < 4; ++mt) {
                int r = wm + mt * 16 + g;
                a[mt][0] = cvt_tf32(As[s][r][k0]);
                a[mt][1] = cvt_tf32(As[s][r + 8][k0]);
                a[mt][2] = cvt_tf32(As[s][r][k0 + 4]);
                a[mt][3] = cvt_tf32(As[s][r + 8][k0 + 4]);
            }
#pragma unroll
            for (int nt = 0; nt < 4; ++nt) {
                int n = wn + nt * 8 + g;
                b[nt][0] = cvt_tf32(Bs[s][n][k0]);
                b[nt][1] = cvt_tf32(Bs[s][n][k0 + 4]);
            }
#pragma unroll
            for (int mt = 0; mt < 4; ++mt)
#pragma unroll
                for (int nt = 0; nt < 4; ++nt) mma8(acc[mt][nt], a[mt], b[nt]);
        }
    }

#pragma unroll
    for (int mt = 0; mt < 4; ++mt) {
#pragma unroll
        for (int nt = 0; nt < 4; ++nt) {
            int row = row0 + wm + mt * 16 + g;
            int col = n0 + wn + nt * 8 + 2 * tig;
            float b0 = __ldg(bias + col), b1 = __ldg(bias + col + 1);
            float v0 = acc[mt][nt][0] + b0, v1 = acc[mt][nt][1] + b1;
            float v2 = acc[mt][nt][2] + b0, v3 = acc[mt][nt][3] + b1;
            if (RELU) {
                v0 = fmaxf(v0, 0.f); v1 = fmaxf(v1, 0.f);
                v2 = fmaxf(v2, 0.f); v3 = fmaxf(v3, 0.f);
            }
            float2 p0 = {v0, v1}, p1 = {v2, v3};
            *(float2*)&C[(size_t)row * LDC + col] = p0;
            *(float2*)&C[(size_t)(row + 8) * LDC + col] = p1;
        }
    }
}

// ============ K3: attention + LN + head (16 rows/block, 256 thr, 2 CTA/SM) ============
#define K3_SMEM_FLOATS 21568
#define K3_SMEM_BYTES (K3_SMEM_FLOATS * 4)

__global__ __launch_bounds__(256) void k3_attn(
    const float* __restrict__ obs,
    const float* __restrict__ Wr, const float* __restrict__ br,
    const float* __restrict__ Win, const float* __restrict__ bin_,
    const float* __restrict__ Wout, const float* __restrict__ bout,
    const float* __restrict__ gamma, const float* __restrict__ beta,
    const float* __restrict__ Wh1, const float* __restrict__ bh1,
    const float* __restrict__ Wh2, const float* __restrict__ bh2,
    float* __restrict__ out_ctx, float* __restrict__ out_ent) {
    extern __shared__ float sm[];
    float* Ts    = sm;             // 16*544 = 8704 (tok, stride 68 per token)
    float* qwS   = Ts + 8704;      // 16*260 = 4160
    float* wbuf  = qwS + 4160;     // 4160
    float* rembS = wbuf + 4160;    // 1024
    float* qS    = rembS + 1024;   // 1024
    float* ctxS  = qS + 1024;      // 1024
    float* attnS = ctxS + 1024;    // 512
    float* rootS = attnS + 512;    // 192
    float* WrS   = rootS + 192;    // 768

    const int tid = threadIdx.x;
    const int lane = tid & 31, w = tid >> 5;
    const int row0 = blockIdx.x * 16;

    // loads: tok tile, root slice, Wr, Wq
    {
        const float* src = g_tok + (size_t)row0 * 512;
#pragma unroll
        for (int l = 0; l < 8; ++l) {
            int idx = (tid + l * 256) * 4;
            int r = idx >> 9, c = idx & 511;
            float4 v = *(const float4*)(src + (size_t)r * 512 + c);
            *(float4*)&Ts[r * 544 + (c >> 6) * 68 + (c & 63)] = v;
        }
    }
    for (int idx = tid; idx < 16 * 11; idx += 256) {
        int r = idx / 11, j = idx % 11;
        int col = (j < 5) ? j : (17 + j);
        rootS[r * 12 + j] = obs[(size_t)(row0 + r) * 376 + col];
    }
    for (int idx = tid; idx < 64 * 11; idx += 256)
        WrS[(idx / 11) * 12 + (idx % 11)] = Wr[idx];
    for (int idx = tid; idx < 4096; idx += 256)
        wbuf[(idx >> 6) * 65 + (idx & 63)] = Win[idx];
    __syncthreads();

    // r_emb + q
#pragma unroll
    for (int rr = 0; rr < 2; ++rr) {
        int r = w * 2 + rr;
#pragma unroll
        for (int half = 0; half < 2; ++half) {
            int e = lane + 32 * half;
            float acc = br[e];
#pragma unroll
            for (int j = 0; j < 11; ++j) acc = fmaf(rootS[r * 12 + j], WrS[e * 12 + j], acc);
            rembS[r * 64 + e] = acc;
        }
    }
    __syncwarp();
#pragma unroll
    for (int rr = 0; rr < 2; ++rr) {
        int r = w * 2 + rr;
#pragma unroll
        for (int half = 0; half < 2; ++half) {
            int e = lane + 32 * half;
            float acc = bin_[e];
#pragma unroll 8
            for (int d = 0; d < 64; ++d) acc = fmaf(rembS[r * 64 + d], wbuf[e * 65 + d], acc);
            qS[r * 64 + e] = acc;
        }
    }
    __syncthreads();
    for (int idx = tid; idx < 4096; idx += 256)  // Wk
        wbuf[(idx >> 6) * 65 + (idx & 63)] = Win[4096 + idx];
    __syncthreads();

    // scores / softmax / entropy / wtok
    {
        const int h = lane >> 3, t = lane & 7;
#pragma unroll
        for (int rr = 0; rr < 2; ++rr) {
            int r = w * 2 + rr;
            size_t row = (size_t)row0 + r;
#pragma unroll
            for (int hh = 0; hh < 4; ++hh)
#pragma unroll
                for (int half = 0; half < 2; ++half) {
                    int j = lane + 32 * half;
                    float acc = 0.f;
#pragma unroll
                    for (int e = 0; e < 16; ++e)
                        acc = fmaf(qS[r * 64 + hh * 16 + e], wbuf[(hh * 16 + e) * 65 + j], acc);
                    qwS[r * 260 + hh * 65 + j] = acc * 0.25f;
                }
            __syncwarp();
            float qbk = 0.f;
#pragma unroll
            for (int e = 0; e < 16; ++e)
                qbk = fmaf(qS[r * 64 + h * 16 + e], bin_[64 + h * 16 + e], qbk);
            float s = qbk * 0.25f;
#pragma unroll 8
            for (int j = 0; j < 64; ++j)
                s = fmaf(Ts[r * 544 + t * 68 + j], qwS[r * 260 + h * 65 + j], s);
            float m = s;
            m = fmaxf(m, __shfl_xor_sync(0xffffffffu, m, 1, 8));
            m = fmaxf(m, __shfl_xor_sync(0xffffffffu, m, 2, 8));
            m = fmaxf(m, __shfl_xor_sync(0xffffffffu, m, 4, 8));
            float ex = expf(s - m);
            float den = ex;
            den += __shfl_xor_sync(0xffffffffu, den, 1, 8);
            den += __shfl_xor_sync(0xffffffffu, den, 2, 8);
            den += __shfl_xor_sync(0xffffffffu, den, 4, 8);
            float a = ex / den;
            attnS[r * 32 + lane] = a;
            float ah = a;
            ah += __shfl_xor_sync(0xffffffffu, ah, 8);
            ah += __shfl_xor_sync(0xffffffffu, ah, 16);
            float aw = fmaxf(ah * 0.25f, 1e-8f);
            float term = -aw * logf(aw);
            term += __shfl_xor_sync(0xffffffffu, term, 1, 8);
            term += __shfl_xor_sync(0xffffffffu, term, 2, 8);
            term += __shfl_xor_sync(0xffffffffu, term, 4, 8);
            if (lane == 0) out_ent[row] = term;
            __syncwarp();
#pragma unroll
            for (int hh = 0; hh < 4; ++hh)
#pragma unroll
                for (int half = 0; half < 2; ++half) {
                    int j = lane + 32 * half;
                    float acc = 0.f;
#pragma unroll
                    for (int tt = 0; tt < 8; ++tt)
                        acc = fmaf(attnS[r * 32 + hh * 8 + tt], Ts[r * 544 + tt * 68 + j], acc);
                    qwS[r * 260 + hh * 65 + j] = acc;
                }
            __syncwarp();
        }
    }
    __syncthreads();
    for (int idx = tid; idx < 4096; idx += 256)  // Wv
        wbuf[(idx >> 6) * 65 + (idx & 63)] = Win[8192 + idx];
    __syncthreads();

    // ctx
#pragma unroll
    for (int rr = 0; rr < 2; ++rr) {
        int r = w * 2 + rr;
#pragma unroll
        for (int half = 0; half < 2; ++half) {
            int d = lane + 32 * half;
            int h = d >> 4;
            float acc = bin_[128 + d];
#pragma unroll 8
            for (int j = 0; j < 64; ++j)
                acc = fmaf(qwS[r * 260 + h * 65 + j], wbuf[d * 65 + j], acc);
            ctxS[r * 64 + d] = acc;
        }
    }
    __syncthreads();
    for (int idx = tid; idx < 4096; idx += 256)  // Wout
        wbuf[(idx >> 6) * 65 + (idx & 63)] = Wout[idx];
    __syncthreads();

    // attn_out + residual + LN
#pragma unroll
    for (int rr = 0; rr < 2; ++rr) {
        int r = w * 2 + rr;
        size_t row = (size_t)row0 + r;
        float x0, x1;
        {
            float acc = bout[lane];
#pragma unroll 8
            for (int d = 0; d < 64; ++d) acc = fmaf(ctxS[r * 64 + d], wbuf[lane * 65 + d], acc);
            x0 = acc + rembS[r * 64 + lane];
        }
        {
            int e = lane + 32;
            float acc = bout[e];
#pragma unroll 8
            for (int d = 0; d < 64; ++d) acc = fmaf(ctxS[r * 64 + d], wbuf[e * 65 + d], acc);
            x1 = acc + rembS[r * 64 + e];
        }
        float ssum = x0 + x1;
#pragma unroll
        for (int o = 16; o > 0; o >>= 1) ssum += __shfl_xor_sync(0xffffffffu, ssum, o);
        float mu = ssum * (1.f / 64.f);
        float d0 = x0 - mu, d1 = x1 - mu;
        float vs = d0 * d0 + d1 * d1;
#pragma unroll
        for (int o = 16; o > 0; o >>= 1) vs += __shfl_xor_sync(0xffffffffu, vs, o);
        float inv = rsqrtf(vs * (1.f / 64.f) + 1e-5f);
        float c0 = fmaf(gamma[lane], d0 * inv, beta[lane]);
        float c1 = fmaf(gamma[lane + 32], d1 * inv, beta[lane + 32]);
        out_ctx[row * 64 + lane] = c0;
        out_ctx[row * 64 + lane + 32] = c1;
        __syncwarp();
        ctxS[r * 64 + lane] = c0;
        ctxS[r * 64 + lane + 32] = c1;
        __syncwarp();
    }
    __syncthreads();
    for (int idx = tid; idx < 2048; idx += 256)  // Wh1
        wbuf[(idx >> 6) * 65 + (idx & 63)] = Wh1[idx];
    __syncthreads();

    // head MLP
#pragma unroll
    for (int rr = 0; rr < 2; ++rr) {
        int r = w * 2 + rr;
        size_t row = (size_t)row0 + r;
        float acc = bh1[lane];
#pragma unroll 8
        for (int d = 0; d < 64; ++d) acc = fmaf(ctxS[r * 64 + d], wbuf[lane * 65 + d], acc);
        float v = fmaxf(acc, 0.f) * Wh2[lane];
#pragma unroll
        for (int o = 16; o > 0; o >>= 1) v += __shfl_xor_sync(0xffffffffu, v, o);
        if (lane == 0) g_raw[row] = v + bh2[0];
    }
}

// ================= batch reductions =================
__global__ void k_reduce_raw() {
    __shared__ float s[256];
    int tid = threadIdx.x;
    int i = blockIdx.x * 512 + tid;
    s[tid] = g_raw[i] + g_raw[i + 256];
    __syncthreads();
    for (int o = 128; o > 0; o >>= 1) {
        if (tid < o) s[tid] += s[tid + o];
        __syncthreads();
    }
    if (tid == 0) g_part[blockIdx.x] = s[0];
}
__global__ void k_finish_raw() {
    __shared__ float s[256];
    int tid = threadIdx.x;
    s[tid] = g_part[tid];
    __syncthreads();
    for (int o = 128; o > 0; o >>= 1) {
        if (tid < o) s[tid] += s[tid + o];
        __syncthreads();
    }
    if (tid == 0) g_scalars[0] = s[0] * (1.f / (float)BATCH);
}
__global__ void k_reduce_lw() {
    __shared__ float s[256];
    int tid = threadIdx.x;
    float mean = g_scalars[0];
    int i = blockIdx.x * 512 + tid;
    s[tid] = expf(0.5f * tanhf(g_raw[i] - mean)) +
             expf(0.5f * tanhf(g_raw[i + 256] - mean));
    __syncthreads();
    for (int o = 128; o > 0; o >>= 1) {
        if (tid < o) s[tid] += s[tid + o];
        __syncthreads();
    }
    if (tid == 0) g_part[blockIdx.x] = s[0];
}
__global__ void k_finish_lw() {
    __shared__ float s[256];
    int tid = threadIdx.x;
    s[tid] = g_part[tid];
    __syncthreads();
    for (int o = 128; o > 0; o >>= 1) {
        if (tid < o) s[tid] += s[tid + o];
        __syncthreads();
    }
    if (tid == 0) g_scalars[1] = fmaxf(s[0] * (1.f / (float)BATCH), 1e-6f);
}
__global__ void k_write_lw(float* __restrict__ out_lw) {
    int i = blockIdx.x * 256 + threadIdx.x;
    float lw = expf(0.5f * tanhf(g_raw[i] - g_scalars[0]));
    out_lw[i] = lw / g_scalars[1];
}

// =====================================================================
extern "C" void kernel_launch(void* const* d_in, const int* in_sizes, int n_in,
                              void* d_out, int out_size) {
    const float* obs   = (const float*)d_in[0];
    const float* W1    = (const float*)d_in[1];
    const float* b1    = (const float*)d_in[2];
    const float* W2    = (const float*)d_in[3];
    const float* b2    = (const float*)d_in[4];
    const float* Wr    = (const float*)d_in[5];
    const float* br    = (const float*)d_in[6];
    const float* Win   = (const float*)d_in[7];
    const float* bin_  = (const float*)d_in[8];
    const float* Wout  = (const float*)d_in[9];
    const float* bout  = (const float*)d_in[10];
    const float* gamma = (const float*)d_in[11];
    const float* beta  = (const float*)d_in[12];
    const float* Wh1   = (const float*)d_in[13];
    const float* bh1   = (const float*)d_in[14];
    const float* Wh2   = (const float*)d_in[15];
    const float* bh2   = (const float*)d_in[16];

    float* out     = (float*)d_out;
    float* out_ctx = out;
    float* out_lw  = out + (size_t)BATCH * 64;
    float* out_ent = out_lw + BATCH;

    cudaFuncSetAttribute(k3_attn, cudaFuncAttributeMaxDynamicSharedMemorySize,
                         K3_SMEM_BYTES);

    float* d_H;
    cudaGetSymbolAddress((void**)&d_H, g_H);
    float* d_tok;
    cudaGetSymbolAddress((void**)&d_tok, g_tok);

    // K1: H = relu(gather(obs) @ W1^T + b1), K=308 (20 k-tiles of 16)
    gemm_tf32<20, true, true, 376, 308, 256>
        <<<dim3(BATCH / 128, 2), 256>>>(obs, W1, b1, d_H);
    // K2: tok = H @ W2^T + b2, K=256 (16 k-tiles)
    gemm_tf32<16, false, false, 0, 256, 512>
        <<<dim3(BATCH / 128, 4), 256>>>(d_H, W2, b2, d_tok);
    // K3: attention + LN + head
    k3_attn<<<BATCH / 16, 256, K3_SMEM_BYTES>>>(
        obs, Wr, br, Win, bin_, Wout, bout, gamma, beta,
        Wh1, bh1, Wh2, bh2, out_ctx, out_ent);
    k_reduce_raw<<<256, 256>>>();
    k_finish_raw<<<1, 256>>>();
    k_reduce_lw<<<256, 256>>>();
    k_finish_lw<<<1, 256>>>();
    k_write_lw<<<BATCH / 256, 256>>>(out_lw);
}

// round 4
// speedup vs baseline: 4.9888x; 1.6278x over previous
#include <cuda_runtime.h>
#include <math.h>

#define BATCH 131072

__device__ float g_H[(size_t)BATCH * 256];
__device__ float g_tok[(size_t)BATCH * 512];
__device__ float g_wtok[(size_t)BATCH * 256];
__device__ float g_remb[(size_t)BATCH * 64];
__device__ float g_raw[BATCH];
__device__ float g_part[256];
__device__ float g_scalars[2];
// folded weights
__device__ float g_A1T[12 * 256];   // [t][hj]
__device__ float g_c1[256];
__device__ float g_G[64 * 256];     // [e][hj]
__device__ float g_cb[64];

// ---------------- tf32 / cp.async helpers ----------------
__device__ __forceinline__ unsigned cvt_tf32(float x) {
    unsigned u;
    asm("cvt.rna.tf32.f32 %0, %1;" : "=r"(u) : "f"(x));
    return u;
}
__device__ __forceinline__ void cp4(unsigned dst, const float* src, unsigned sz) {
    asm volatile("cp.async.ca.shared.global [%0], [%1], 4, %2;" ::
                 "r"(dst), "l"(src), "r"(sz));
}
__device__ __forceinline__ void cp16(unsigned dst, const float* src) {
    asm volatile("cp.async.cg.shared.global [%0], [%1], 16;" ::
                 "r"(dst), "l"(src));
}
#define CP_COMMIT asm volatile("cp.async.commit_group;")
#define CP_WAIT0  asm volatile("cp.async.wait_group 0;")

__device__ __forceinline__ void mma8(float* d, const unsigned* a, const unsigned* b) {
    asm volatile(
        "mma.sync.aligned.m16n8k8.row.col.f32.tf32.tf32.f32 "
        "{%0,%1,%2,%3}, {%4,%5,%6,%7}, {%8,%9}, {%0,%1,%2,%3};"
        : "+f"(d[0]), "+f"(d[1]), "+f"(d[2]), "+f"(d[3])
        : "r"(a[0]), "r"(a[1]), "r"(a[2]), "r"(a[3]), "r"(b[0]), "r"(b[1]));
}

// ============ K0: fold precompute ============
__global__ __launch_bounds__(256) void k0_fold(
    const float* __restrict__ Wr, const float* __restrict__ br,
    const float* __restrict__ Win, const float* __restrict__ bin_,
    const float* __restrict__ Wout, const float* __restrict__ bout) {
    __shared__ float QW[64 * 12];
    __shared__ float qsS[64];
    const int tid = threadIdx.x, bx = blockIdx.x;

    if (bx == 0) {
        for (int idx = tid; idx < 704; idx += 256) {
            int e = idx / 11, t = idx % 11;
            float acc = 0.f;
            for (int d = 0; d < 64; ++d) acc = fmaf(Win[e * 64 + d], Wr[d * 11 + t], acc);
            QW[e * 12 + t] = acc;
        }
        for (int idx = tid; idx < 64; idx += 256) {
            float acc = bin_[idx];
            for (int d = 0; d < 64; ++d) acc = fmaf(Win[idx * 64 + d], br[d], acc);
            qsS[idx] = acc;
        }
        __syncthreads();
        for (int idx = tid; idx < 2816; idx += 256) {
            int hj = idx / 11, t = idx % 11;
            int h = hj >> 6, j = hj & 63;
            float acc = 0.f;
            for (int e = 0; e < 16; ++e) {
                int x = h * 16 + e;
                acc = fmaf(Win[4096 + x * 64 + j], QW[x * 12 + t], acc);
            }
            g_A1T[t * 256 + hj] = acc;
        }
        for (int idx = tid; idx < 256; idx += 256) {
            int h = idx >> 6, j = idx & 63;
            float acc = 0.f;
            for (int e = 0; e < 16; ++e) {
                int x = h * 16 + e;
                acc = fmaf(Win[4096 + x * 64 + j], qsS[x], acc);
            }
            g_c1[idx] = acc;
        }
        for (int idx = tid; idx < 64; idx += 256) {
            float acc = bout[idx];
            for (int d = 0; d < 64; ++d) acc = fmaf(Wout[idx * 64 + d], bin_[128 + d], acc);
            g_cb[idx] = acc;
        }
    }
    // all 8 blocks: G rows e in [bx*8, bx*8+8)
    for (int idx = tid; idx < 2048; idx += 256) {
        int e = bx * 8 + (idx >> 8);
        int hj = idx & 255, h = hj >> 6, j = hj & 63;
        float acc = 0.f;
        for (int d = 0; d < 16; ++d)
            acc = fmaf(Wout[e * 64 + h * 16 + d], Win[8192 + (h * 16 + d) * 64 + j], acc);
        g_G[e * 256 + hj] = acc;
    }
}

// ============ tf32 tile GEMM 128x128 (K1/K2, unchanged) ============
template <int KT, bool GATHER, bool RELU, int LDA, int KROW, int LDC>
__global__ __launch_bounds__(256) void gemm_tf32(const float* __restrict__ A,
                                                 const float* __restrict__ W,
                                                 const float* __restrict__ bias,
                                                 float* __restrict__ C) {
    __shared__ float As[2][128][20];
    __shared__ float Bs[2][128][20];
    const int tid = threadIdx.x;
    const int lane = tid & 31, w = tid >> 5;
    const int row0 = blockIdx.x * 128, n0 = blockIdx.y * 128;
    const int wm = (w & 1) * 64, wn = (w >> 1) * 32;
    const int g = lane >> 2, tig = lane & 3;

    float acc[4][4][4] = {};

    auto loadTile = [&](int s, int kt) {
        const int kb = kt * 16;
        if (GATHER) {
#pragma unroll
            for (int l = 0; l < 8; ++l) {
                int idx = tid + l * 256;
                int r = idx >> 4, kk = idx & 15;
                int k = kb + kk;
                int col = (k < 224) ? (45 + k) : (68 + k);
                const float* src = A + (size_t)(row0 + r) * LDA + ((k < KROW) ? col : 0);
                cp4((unsigned)__cvta_generic_to_shared(&As[s][r][kk]), src,
                    (k < KROW) ? 4u : 0u);
            }
#pragma unroll
            for (int l = 0; l < 8; ++l) {
                int idx = tid + l * 256;
                int n = idx >> 4, kk = idx & 15;
                int k = kb + kk;
                const float* src = W + (size_t)(n0 + n) * KROW + ((k < KROW) ? k : 0);
                cp4((unsigned)__cvta_generic_to_shared(&Bs[s][n][kk]), src,
                    (k < KROW) ? 4u : 0u);
            }
        } else {
#pragma unroll
            for (int l = 0; l < 2; ++l) {
                int idx = tid + l * 256;
                int r = idx >> 2, c = (idx & 3) * 4;
                cp16((unsigned)__cvta_generic_to_shared(&As[s][r][c]),
                     A + (size_t)(row0 + r) * KROW + kb + c);
            }
#pragma unroll
            for (int l = 0; l < 2; ++l) {
                int idx = tid + l * 256;
                int n = idx >> 2, c = (idx & 3) * 4;
                cp16((unsigned)__cvta_generic_to_shared(&Bs[s][n][c]),
                     W + (size_t)(n0 + n) * KROW + kb + c);
            }
        }
    };

    loadTile(0, 0);
    CP_COMMIT;

    for (int kt = 0; kt < KT; ++kt) {
        CP_WAIT0;
        __syncthreads();
        if (kt + 1 < KT) {
            loadTile((kt + 1) & 1, kt + 1);
            CP_COMMIT;
        }
        const int s = kt & 1;
#pragma unroll
        for (int km = 0; km < 2; ++km) {
            unsigned a[4][4], b[4][2];
            const int k0 = km * 8 + tig;
#pragma unroll
            for (int mt = 0; mt < 4; ++mt) {
                int r = wm + mt * 16 + g;
                a[mt][0] = cvt_tf32(As[s][r][k0]);
                a[mt][1] = cvt_tf32(As[s][r + 8][k0]);
                a[mt][2] = cvt_tf32(As[s][r][k0 + 4]);
                a[mt][3] = cvt_tf32(As[s][r + 8][k0 + 4]);
            }
#pragma unroll
            for (int nt = 0; nt < 4; ++nt) {
                int n = wn + nt * 8 + g;
                b[nt][0] = cvt_tf32(Bs[s][n][k0]);
                b[nt][1] = cvt_tf32(Bs[s][n][k0 + 4]);
            }
#pragma unroll
            for (int mt = 0; mt < 4; ++mt)
#pragma unroll
                for (int nt = 0; nt < 4; ++nt) mma8(acc[mt][nt], a[mt], b[nt]);
        }
    }

#pragma unroll
    for (int mt = 0; mt < 4; ++mt) {
#pragma unroll
        for (int nt = 0; nt < 4; ++nt) {
            int row = row0 + wm + mt * 16 + g;
            int col = n0 + wn + nt * 8 + 2 * tig;
            float b0 = __ldg(bias + col), b1 = __ldg(bias + col + 1);
            float v0 = acc[mt][nt][0] + b0, v1 = acc[mt][nt][1] + b1;
            float v2 = acc[mt][nt][2] + b0, v3 = acc[mt][nt][3] + b1;
            if (RELU) {
                v0 = fmaxf(v0, 0.f); v1 = fmaxf(v1, 0.f);
                v2 = fmaxf(v2, 0.f); v3 = fmaxf(v3, 0.f);
            }
            float2 p0 = {v0, v1}, p1 = {v2, v3};
            *(float2*)&C[(size_t)row * LDC + col] = p0;
            *(float2*)&C[(size_t)(row + 8) * LDC + col] = p1;
        }
    }
}

// ============ K3a: root->r_emb, s1, scores, softmax, entropy, wtok ============
#define K3A_SMEM_FLOATS 17664
#define K3A_SMEM_BYTES (K3A_SMEM_FLOATS * 4)

__global__ __launch_bounds__(256) void k3a_attn(
    const float* __restrict__ obs,
    const float* __restrict__ Wr, const float* __restrict__ br,
    float* __restrict__ out_ent) {
    extern __shared__ float sm[];
    float* toks  = sm;              // 16*544 = 8704
    float* s1S   = toks + 8704;     // 16*260 = 4160
    float* A1T   = s1S + 4160;      // 12*256 = 3072
    float* c1S   = A1T + 3072;      // 256
    float* WrS   = c1S + 256;       // 768
    float* rootS = WrS + 768;       // 192
    float* attnS = rootS + 192;     // 512

    const int tid = threadIdx.x;
    const int lane = tid & 31, w = tid >> 5;
    const int row0 = blockIdx.x * 16;

    {
        const float* src = g_tok + (size_t)row0 * 512;
#pragma unroll
        for (int l = 0; l < 8; ++l) {
            int idx = (tid + l * 256) * 4;
            int r = idx >> 9, c = idx & 511;
            float4 v = *(const float4*)(src + (size_t)r * 512 + c);
            *(float4*)&toks[r * 544 + (c >> 6) * 68 + (c & 63)] = v;
        }
    }
    for (int idx = tid; idx < 3072; idx += 256) A1T[idx] = g_A1T[idx];
    if (tid < 256) c1S[tid] = g_c1[tid];
    for (int idx = tid; idx < 704; idx += 256)
        WrS[(idx / 11) * 12 + (idx % 11)] = Wr[idx];
    for (int idx = tid; idx < 176; idx += 256) {
        int r = idx / 11, j = idx % 11;
        int col = (j < 5) ? j : (17 + j);
        rootS[r * 12 + j] = obs[(size_t)(row0 + r) * 376 + col];
    }
    __syncthreads();

    const int h = lane >> 3, t = lane & 7;
#pragma unroll
    for (int rr = 0; rr < 2; ++rr) {
        const int r = w * 2 + rr;
        const size_t row = (size_t)row0 + r;
        // r_emb -> gmem
#pragma unroll
        for (int half = 0; half < 2; ++half) {
            int e = lane + 32 * half;
            float acc = br[e];
#pragma unroll
            for (int j = 0; j < 11; ++j) acc = fmaf(rootS[r * 12 + j], WrS[e * 12 + j], acc);
            g_remb[row * 64 + e] = acc;
        }
        // s1 = A1*root + c1
#pragma unroll
        for (int o = 0; o < 8; ++o) {
            int hj = lane + 32 * o;
            float acc = c1S[hj];
#pragma unroll
            for (int tt = 0; tt < 11; ++tt)
                acc = fmaf(rootS[r * 12 + tt], A1T[tt * 256 + hj], acc);
            s1S[r * 260 + (hj >> 6) * 65 + (hj & 63)] = acc;
        }
        __syncwarp();
        // scores + softmax + entropy
        float s = 0.f;
#pragma unroll 8
        for (int j = 0; j < 64; ++j)
            s = fmaf(s1S[r * 260 + h * 65 + j], toks[r * 544 + t * 68 + j], s);
        s *= 0.25f;
        float m = s;
        m = fmaxf(m, __shfl_xor_sync(0xffffffffu, m, 1, 8));
        m = fmaxf(m, __shfl_xor_sync(0xffffffffu, m, 2, 8));
        m = fmaxf(m, __shfl_xor_sync(0xffffffffu, m, 4, 8));
        float ex = expf(s - m);
        float den = ex;
        den += __shfl_xor_sync(0xffffffffu, den, 1, 8);
        den += __shfl_xor_sync(0xffffffffu, den, 2, 8);
        den += __shfl_xor_sync(0xffffffffu, den, 4, 8);
        float a = ex / den;
        attnS[r * 32 + lane] = a;
        float ah = a;
        ah += __shfl_xor_sync(0xffffffffu, ah, 8);
        ah += __shfl_xor_sync(0xffffffffu, ah, 16);
        float aw = fmaxf(ah * 0.25f, 1e-8f);
        float term = -aw * logf(aw);
        term += __shfl_xor_sync(0xffffffffu, term, 1, 8);
        term += __shfl_xor_sync(0xffffffffu, term, 2, 8);
        term += __shfl_xor_sync(0xffffffffu, term, 4, 8);
        if (lane == 0) out_ent[row] = term;
        __syncwarp();
        // wtok -> gmem
#pragma unroll
        for (int o = 0; o < 8; ++o) {
            int hj = lane + 32 * o;
            int h2 = hj >> 6, j = hj & 63;
            float acc = 0.f;
#pragma unroll
            for (int tt = 0; tt < 8; ++tt)
                acc = fmaf(attnS[r * 32 + h2 * 8 + tt], toks[r * 544 + tt * 68 + j], acc);
            g_wtok[row * 256 + hj] = acc;
        }
    }
}

// ============ K4: y = wtok@G^T + cb, then residual + LN + head (fused) ============
#define K4_SMEM_FLOATS 10784
#define K4_SMEM_BYTES (K4_SMEM_FLOATS * 4)

__global__ __launch_bounds__(256) void k4_out_ln_head(
    const float* __restrict__ gamma, const float* __restrict__ beta,
    const float* __restrict__ Wh1, const float* __restrict__ bh1,
    const float* __restrict__ Wh2, const float* __restrict__ bh2,
    float* __restrict__ out_ctx) {
    extern __shared__ float sm[];
    float* As = sm;                 // 2*128*20 = 5120
    float* Bs = sm + 5120;          // 2*64*20 = 2560
    float* ys = sm;                 // epi: 128*68 = 8704
    float* Wh1S = sm + 8704;        // 32*65 = 2080

    const int tid = threadIdx.x;
    const int lane = tid & 31, w = tid >> 5;
    const int row0 = blockIdx.x * 128;
    const int wm = (w & 3) * 32, wn = (w >> 2) * 32;
    const int g = lane >> 2, tig = lane & 3;

    float acc[2][4][4] = {};

    auto loadTile = [&](int s, int kt) {
        const int kb = kt * 16;
#pragma unroll
        for (int l = 0; l < 2; ++l) {
            int idx = tid + l * 256;
            int r = idx >> 2, c = (idx & 3) * 4;
            cp16((unsigned)__cvta_generic_to_shared(&As[(s * 128 + r) * 20 + c]),
                 g_wtok + (size_t)(row0 + r) * 256 + kb + c);
        }
        {
            int r = tid >> 2, c = (tid & 3) * 4;
            cp16((unsigned)__cvta_generic_to_shared(&Bs[(s * 64 + r) * 20 + c]),
                 g_G + (size_t)r * 256 + kb + c);
        }
    };

    loadTile(0, 0);
    CP_COMMIT;
    for (int kt = 0; kt < 16; ++kt) {
        CP_WAIT0;
        __syncthreads();
        if (kt + 1 < 16) {
            loadTile((kt + 1) & 1, kt + 1);
            CP_COMMIT;
        }
        const int s = kt & 1;
#pragma unroll
        for (int km = 0; km < 2; ++km) {
            unsigned a[2][4], b[4][2];
            const int k0 = km * 8 + tig;
#pragma unroll
            for (int mt = 0; mt < 2; ++mt) {
                int r = wm + mt * 16 + g;
                a[mt][0] = cvt_tf32(As[(s * 128 + r) * 20 + k0]);
                a[mt][1] = cvt_tf32(As[(s * 128 + r + 8) * 20 + k0]);
                a[mt][2] = cvt_tf32(As[(s * 128 + r) * 20 + k0 + 4]);
                a[mt][3] = cvt_tf32(As[(s * 128 + r + 8) * 20 + k0 + 4]);
            }
#pragma unroll
            for (int nt = 0; nt < 4; ++nt) {
                int n = wn + nt * 8 + g;
                b[nt][0] = cvt_tf32(Bs[(s * 64 + n) * 20 + k0]);
                b[nt][1] = cvt_tf32(Bs[(s * 64 + n) * 20 + k0 + 4]);
            }
#pragma unroll
            for (int mt = 0; mt < 2; ++mt)
#pragma unroll
                for (int nt = 0; nt < 4; ++nt) mma8(acc[mt][nt], a[mt], b[nt]);
        }
    }
    __syncthreads();   // done with As/Bs; reuse as ys

#pragma unroll
    for (int mt = 0; mt < 2; ++mt) {
#pragma unroll
        for (int nt = 0; nt < 4; ++nt) {
            int r = wm + mt * 16 + g;
            int col = wn + nt * 8 + 2 * tig;
            float c0 = g_cb[col], c1 = g_cb[col + 1];
            ys[r * 68 + col]           = acc[mt][nt][0] + c0;
            ys[r * 68 + col + 1]       = acc[mt][nt][1] + c1;
            ys[(r + 8) * 68 + col]     = acc[mt][nt][2] + c0;
            ys[(r + 8) * 68 + col + 1] = acc[mt][nt][3] + c1;
        }
    }
    for (int idx = tid; idx < 2048; idx += 256)
        Wh1S[(idx >> 6) * 65 + (idx & 63)] = Wh1[idx];
    __syncthreads();

    const float gm0 = gamma[lane], gm1 = gamma[lane + 32];
    const float bt0 = beta[lane],  bt1 = beta[lane + 32];
    const float bh1v = bh1[lane], wh2v = Wh2[lane], bh2v = bh2[0];

#pragma unroll 2
    for (int rr = 0; rr < 16; ++rr) {
        const int r = w * 16 + rr;
        const size_t row = (size_t)row0 + r;
        float x0 = ys[r * 68 + lane]      + g_remb[row * 64 + lane];
        float x1 = ys[r * 68 + lane + 32] + g_remb[row * 64 + lane + 32];
        float ssum = x0 + x1;
#pragma unroll
        for (int o = 16; o > 0; o >>= 1) ssum += __shfl_xor_sync(0xffffffffu, ssum, o);
        float mu = ssum * (1.f / 64.f);
        float d0 = x0 - mu, d1 = x1 - mu;
        float vs = d0 * d0 + d1 * d1;
#pragma unroll
        for (int o = 16; o > 0; o >>= 1) vs += __shfl_xor_sync(0xffffffffu, vs, o);
        float inv = rsqrtf(vs * (1.f / 64.f) + 1e-5f);
        float c0 = fmaf(gm0, d0 * inv, bt0);
        float c1 = fmaf(gm1, d1 * inv, bt1);
        out_ctx[row * 64 + lane] = c0;
        out_ctx[row * 64 + lane + 32] = c1;
        ys[r * 68 + lane] = c0;
        ys[r * 68 + lane + 32] = c1;
        __syncwarp();
        float acc2 = bh1v;
#pragma unroll 8
        for (int d = 0; d < 64; ++d)
            acc2 = fmaf(ys[r * 68 + d], Wh1S[lane * 65 + d], acc2);
        float v = fmaxf(acc2, 0.f) * wh2v;
#pragma unroll
        for (int o = 16; o > 0; o >>= 1) v += __shfl_xor_sync(0xffffffffu, v, o);
        if (lane == 0) g_raw[row] = v + bh2v;
        __syncwarp();
    }
}

// ================= batch reductions =================
__global__ void k_reduce_raw() {
    __shared__ float s[256];
    int tid = threadIdx.x;
    int i = blockIdx.x * 512 + tid;
    s[tid] = g_raw[i] + g_raw[i + 256];
    __syncthreads();
    for (int o = 128; o > 0; o >>= 1) {
        if (tid < o) s[tid] += s[tid + o];
        __syncthreads();
    }
    if (tid == 0) g_part[blockIdx.x] = s[0];
}
__global__ void k_finish_raw() {
    __shared__ float s[256];
    int tid = threadIdx.x;
    s[tid] = g_part[tid];
    __syncthreads();
    for (int o = 128; o > 0; o >>= 1) {
        if (tid < o) s[tid] += s[tid + o];
        __syncthreads();
    }
    if (tid == 0) g_scalars[0] = s[0] * (1.f / (float)BATCH);
}
__global__ void k_reduce_lw() {
    __shared__ float s[256];
    int tid = threadIdx.x;
    float mean = g_scalars[0];
    int i = blockIdx.x * 512 + tid;
    s[tid] = expf(0.5f * tanhf(g_raw[i] - mean)) +
             expf(0.5f * tanhf(g_raw[i + 256] - mean));
    __syncthreads();
    for (int o = 128; o > 0; o >>= 1) {
        if (tid < o) s[tid] += s[tid + o];
        __syncthreads();
    }
    if (tid == 0) g_part[blockIdx.x] = s[0];
}
__global__ void k_finish_lw() {
    __shared__ float s[256];
    int tid = threadIdx.x;
    s[tid] = g_part[tid];
    __syncthreads();
    for (int o = 128; o > 0; o >>= 1) {
        if (tid < o) s[tid] += s[tid + o];
        __syncthreads();
    }
    if (tid == 0) g_scalars[1] = fmaxf(s[0] * (1.f / (float)BATCH), 1e-6f);
}
__global__ void k_write_lw(float* __restrict__ out_lw) {
    int i = blockIdx.x * 256 + threadIdx.x;
    float lw = expf(0.5f * tanhf(g_raw[i] - g_scalars[0]));
    out_lw[i] = lw / g_scalars[1];
}

// =====================================================================
extern "C" void kernel_launch(void* const* d_in, const int* in_sizes, int n_in,
                              void* d_out, int out_size) {
    const float* obs   = (const float*)d_in[0];
    const float* W1    = (const float*)d_in[1];
    const float* b1    = (const float*)d_in[2];
    const float* W2    = (const float*)d_in[3];
    const float* b2    = (const float*)d_in[4];
    const float* Wr    = (const float*)d_in[5];
    const float* br    = (const float*)d_in[6];
    const float* Win   = (const float*)d_in[7];
    const float* bin_  = (const float*)d_in[8];
    const float* Wout  = (const float*)d_in[9];
    const float* bout  = (const float*)d_in[10];
    const float* gamma = (const float*)d_in[11];
    const float* beta  = (const float*)d_in[12];
    const float* Wh1   = (const float*)d_in[13];
    const float* bh1   = (const float*)d_in[14];
    const float* Wh2   = (const float*)d_in[15];
    const float* bh2   = (const float*)d_in[16];

    float* out     = (float*)d_out;
    float* out_ctx = out;
    float* out_lw  = out + (size_t)BATCH * 64;
    float* out_ent = out_lw + BATCH;

    cudaFuncSetAttribute(k3a_attn, cudaFuncAttributeMaxDynamicSharedMemorySize,
                         K3A_SMEM_BYTES);
    cudaFuncSetAttribute(k4_out_ln_head, cudaFuncAttributeMaxDynamicSharedMemorySize,
                         K4_SMEM_BYTES);

    float* d_H;   cudaGetSymbolAddress((void**)&d_H, g_H);
    float* d_tok; cudaGetSymbolAddress((void**)&d_tok, g_tok);

    k0_fold<<<8, 256>>>(Wr, br, Win, bin_, Wout, bout);
    gemm_tf32<20, true, true, 376, 308, 256>
        <<<dim3(BATCH / 128, 2), 256>>>(obs, W1, b1, d_H);
    gemm_tf32<16, false, false, 0, 256, 512>
        <<<dim3(BATCH / 128, 4), 256>>>(d_H, W2, b2, d_tok);
    k3a_attn<<<BATCH / 16, 256, K3A_SMEM_BYTES>>>(obs, Wr, br, out_ent);
    k4_out_ln_head<<<BATCH / 128, 256, K4_SMEM_BYTES>>>(
        gamma, beta, Wh1, bh1, Wh2, bh2, out_ctx);
    k_reduce_raw<<<256, 256>>>();
    k_finish_raw<<<1, 256>>>();
    k_reduce_lw<<<256, 256>>>();
    k_finish_lw<<<1, 256>>>();
    k_write_lw<<<BATCH / 256, 256>>>(out_lw);
}

// round 7
// speedup vs baseline: 5.1683x; 1.0360x over previous
#include <cuda_runtime.h>
#include <math.h>

#define BATCH 131072

__device__ float g_H[(size_t)BATCH * 256];
__device__ float g_tok[(size_t)BATCH * 512];
__device__ float g_wtok[(size_t)BATCH * 256];
__device__ float g_raw[BATCH];
__device__ float g_part[256];
__device__ float g_scalars[2];
// folded weights
__device__ float g_A1T[12 * 256];   // [t][hj]
__device__ float g_c1[256];
__device__ float g_G[64 * 256];     // [e][hj]
__device__ float g_cb[64];

// ---------------- tf32 / cp.async helpers ----------------
__device__ __forceinline__ unsigned cvt_tf32(float x) {
    unsigned u;
    asm("cvt.rna.tf32.f32 %0, %1;" : "=r"(u) : "f"(x));
    return u;
}
__device__ __forceinline__ void cp4(unsigned dst, const float* src, unsigned sz) {
    asm volatile("cp.async.ca.shared.global [%0], [%1], 4, %2;" ::
                 "r"(dst), "l"(src), "r"(sz));
}
__device__ __forceinline__ void cp16(unsigned dst, const float* src) {
    asm volatile("cp.async.cg.shared.global [%0], [%1], 16;" ::
                 "r"(dst), "l"(src));
}
__device__ __forceinline__ void cp16z(unsigned dst, const float* src, unsigned sz) {
    asm volatile("cp.async.cg.shared.global [%0], [%1], 16, %2;" ::
                 "r"(dst), "l"(src), "r"(sz));
}
#define CP_COMMIT asm volatile("cp.async.commit_group;")
#define CP_WAIT0  asm volatile("cp.async.wait_group 0;")

__device__ __forceinline__ void mma8(float* d, const unsigned* a, const unsigned* b) {
    asm volatile(
        "mma.sync.aligned.m16n8k8.row.col.f32.tf32.tf32.f32 "
        "{%0,%1,%2,%3}, {%4,%5,%6,%7}, {%8,%9}, {%0,%1,%2,%3};"
        : "+f"(d[0]), "+f"(d[1]), "+f"(d[2]), "+f"(d[3])
        : "r"(a[0]), "r"(a[1]), "r"(a[2]), "r"(a[3]), "r"(b[0]), "r"(b[1]));
}

// ============ K0: fold precompute ============
__global__ __launch_bounds__(256) void k0_fold(
    const float* __restrict__ Wr, const float* __restrict__ br,
    const float* __restrict__ Win, const float* __restrict__ bin_,
    const float* __restrict__ Wout, const float* __restrict__ bout) {
    __shared__ float QW[64 * 12];
    __shared__ float qsS[64];
    const int tid = threadIdx.x, bx = blockIdx.x;

    if (bx == 0) {
        for (int idx = tid; idx < 704; idx += 256) {
            int e = idx / 11, t = idx % 11;
            float acc = 0.f;
            for (int d = 0; d < 64; ++d) acc = fmaf(Win[e * 64 + d], Wr[d * 11 + t], acc);
            QW[e * 12 + t] = acc;
        }
        for (int idx = tid; idx < 64; idx += 256) {
            float acc = bin_[idx];
            for (int d = 0; d < 64; ++d) acc = fmaf(Win[idx * 64 + d], br[d], acc);
            qsS[idx] = acc;
        }
        __syncthreads();
        for (int idx = tid; idx < 2816; idx += 256) {
            int hj = idx / 11, t = idx % 11;
            int h = hj >> 6, j = hj & 63;
            float acc = 0.f;
            for (int e = 0; e < 16; ++e) {
                int x = h * 16 + e;
                acc = fmaf(Win[4096 + x * 64 + j], QW[x * 12 + t], acc);
            }
            g_A1T[t * 256 + hj] = acc;
        }
        for (int idx = tid; idx < 256; idx += 256) {
            int h = idx >> 6, j = idx & 63;
            float acc = 0.f;
            for (int e = 0; e < 16; ++e) {
                int x = h * 16 + e;
                acc = fmaf(Win[4096 + x * 64 + j], qsS[x], acc);
            }
            g_c1[idx] = acc;
        }
        for (int idx = tid; idx < 64; idx += 256) {
            float acc = bout[idx];
            for (int d = 0; d < 64; ++d) acc = fmaf(Wout[idx * 64 + d], bin_[128 + d], acc);
            g_cb[idx] = acc;
        }
    }
    for (int idx = tid; idx < 2048; idx += 256) {
        int e = bx * 8 + (idx >> 8);
        int hj = idx & 255, h = hj >> 6, j = hj & 63;
        float acc = 0.f;
        for (int d = 0; d < 16; ++d)
            acc = fmaf(Wout[e * 64 + h * 16 + d], Win[8192 + (h * 16 + d) * 64 + j], acc);
        g_G[e * 256 + hj] = acc;
    }
}

// ============ tf32 tile GEMM 128x128 ============
template <int KT, bool GATHER, bool RELU, int LDA, int KROW, int LDC>
__global__ __launch_bounds__(256) void gemm_tf32(const float* __restrict__ A,
                                                 const float* __restrict__ W,
                                                 const float* __restrict__ bias,
                                                 float* __restrict__ C) {
    __shared__ float As[2][128][20];
    __shared__ float Bs[2][128][20];
    const int tid = threadIdx.x;
    const int lane = tid & 31, w = tid >> 5;
    const int row0 = blockIdx.x * 128, n0 = blockIdx.y * 128;
    const int wm = (w & 1) * 64, wn = (w >> 1) * 32;
    const int g = lane >> 2, tig = lane & 3;

    float acc[4][4][4] = {};

    auto loadTile = [&](int s, int kt) {
        const int kb = kt * 16;
        if (GATHER) {
#pragma unroll
            for (int l = 0; l < 8; ++l) {
                int idx = tid + l * 256;
                int r = idx >> 4, kk = idx & 15;
                int k = kb + kk;
                int col = (k < 224) ? (45 + k) : (68 + k);
                const float* src = A + (size_t)(row0 + r) * LDA + ((k < KROW) ? col : 0);
                cp4((unsigned)__cvta_generic_to_shared(&As[s][r][kk]), src,
                    (k < KROW) ? 4u : 0u);
            }
            // W tiles: rows 4-float aligned -> 16B cp.async with zfill tail
#pragma unroll
            for (int l = 0; l < 2; ++l) {
                int idx = tid + l * 256;
                int n = idx >> 2, c = (idx & 3) * 4;
                int k = kb + c;
                cp16z((unsigned)__cvta_generic_to_shared(&Bs[s][n][c]),
                      W + (size_t)(n0 + n) * KROW + ((k < KROW) ? k : 0),
                      (k + 4 <= KROW) ? 16u : 0u);
            }
        } else {
#pragma unroll
            for (int l = 0; l < 2; ++l) {
                int idx = tid + l * 256;
                int r = idx >> 2, c = (idx & 3) * 4;
                cp16((unsigned)__cvta_generic_to_shared(&As[s][r][c]),
                     A + (size_t)(row0 + r) * KROW + kb + c);
            }
#pragma unroll
            for (int l = 0; l < 2; ++l) {
                int idx = tid + l * 256;
                int n = idx >> 2, c = (idx & 3) * 4;
                cp16((unsigned)__cvta_generic_to_shared(&Bs[s][n][c]),
                     W + (size_t)(n0 + n) * KROW + kb + c);
            }
        }
    };

    loadTile(0, 0);
    CP_COMMIT;

    for (int kt = 0; kt < KT; ++kt) {
        CP_WAIT0;
        __syncthreads();
        if (kt + 1 < KT) {
            loadTile((kt + 1) & 1, kt + 1);
            CP_COMMIT;
        }
        const int s = kt & 1;
#pragma unroll
        for (int km = 0; km < 2; ++km) {
            unsigned a[4][4], b[4][2];
            const int k0 = km * 8 + tig;
#pragma unroll
            for (int mt = 0; mt < 4; ++mt) {
                int r = wm + mt * 16 + g;
                a[mt][0] = cvt_tf32(As[s][r][k0]);
                a[mt][1] = cvt_tf32(As[s][r + 8][k0]);
                a[mt][2] = cvt_tf32(As[s][r][k0 + 4]);
                a[mt][3] = cvt_tf32(As[s][r + 8][k0 + 4]);
            }
#pragma unroll
            for (int nt = 0; nt < 4; ++nt) {
                int n = wn + nt * 8 + g;
                b[nt][0] = cvt_tf32(Bs[s][n][k0]);
                b[nt][1] = cvt_tf32(Bs[s][n][k0 + 4]);
            }
#pragma unroll
            for (int mt = 0; mt < 4; ++mt)
#pragma unroll
                for (int nt = 0; nt < 4; ++nt) mma8(acc[mt][nt], a[mt], b[nt]);
        }
    }

#pragma unroll
    for (int mt = 0; mt < 4; ++mt) {
#pragma unroll
        for (int nt = 0; nt < 4; ++nt) {
            int row = row0 + wm + mt * 16 + g;
            int col = n0 + wn + nt * 8 + 2 * tig;
            float b0 = __ldg(bias + col), b1 = __ldg(bias + col + 1);
            float v0 = acc[mt][nt][0] + b0, v1 = acc[mt][nt][1] + b1;
            float v2 = acc[mt][nt][2] + b0, v3 = acc[mt][nt][3] + b1;
            if (RELU) {
                v0 = fmaxf(v0, 0.f); v1 = fmaxf(v1, 0.f);
                v2 = fmaxf(v2, 0.f); v3 = fmaxf(v3, 0.f);
            }
            float2 p0 = {v0, v1}, p1 = {v2, v3};
            *(float2*)&C[(size_t)row * LDC + col] = p0;
            *(float2*)&C[(size_t)(row + 8) * LDC + col] = p1;
        }
    }
}

// ============ K3a: s1, scores, softmax, entropy, wtok (vectorized) ============
#define K3A_SMEM_FLOATS 17088
#define K3A_SMEM_BYTES (K3A_SMEM_FLOATS * 4)

__global__ __launch_bounds__(256) void k3a_attn(const float* __restrict__ obs,
                                                float* __restrict__ out_ent) {
    extern __shared__ float sm[];
    float* toks  = sm;              // 16*544 = 8704
    float* s1S   = toks + 8704;     // 16*272 = 4352
    float* A1T   = s1S + 4352;      // 3072
    float* c1S   = A1T + 3072;      // 256
    float* rootS = c1S + 256;       // 192
    float* attnS = rootS + 192;     // 512

    const int tid = threadIdx.x;
    const int lane = tid & 31, w = tid >> 5;
    const int row0 = blockIdx.x * 16;

    {
        const float* src = g_tok + (size_t)row0 * 512;
#pragma unroll
        for (int l = 0; l < 8; ++l) {
            int idx = (tid + l * 256) * 4;
            int r = idx >> 9, c = idx & 511;
            float4 v = *(const float4*)(src + (size_t)r * 512 + c);
            *(float4*)&toks[r * 544 + (c >> 6) * 68 + (c & 63)] = v;
        }
    }
    for (int idx = tid; idx < 768; idx += 256)
        *(float4*)&A1T[idx * 4] = *(const float4*)&g_A1T[idx * 4];
    if (tid < 64) *(float4*)&c1S[tid * 4] = *(const float4*)&g_c1[tid * 4];
    for (int idx = tid; idx < 176; idx += 256) {
        int r = idx / 11, j = idx % 11;
        int col = (j < 5) ? j : (17 + j);
        rootS[r * 12 + j] = obs[(size_t)(row0 + r) * 376 + col];
    }
    __syncthreads();

    const int h = lane >> 3, t = lane & 7;
    const int hh = lane >> 3;          // head for wtok (j-block = lane*8)
    const int jb = (lane * 8) & 63;    // j offset within token
#pragma unroll
    for (int rr = 0; rr < 2; ++rr) {
        const int r = w * 2 + rr;
        const size_t row = (size_t)row0 + r;
        // s1 = A1*root + c1 (8 outputs/lane) into padded [h][68]
#pragma unroll
        for (int o = 0; o < 8; ++o) {
            int hj = lane + 32 * o;
            float acc = c1S[hj];
#pragma unroll
            for (int tt = 0; tt < 11; ++tt)
                acc = fmaf(rootS[r * 12 + tt], A1T[tt * 256 + hj], acc);
            s1S[r * 272 + (hj >> 6) * 68 + (hj & 63)] = acc;
        }
        __syncwarp();
        // scores: float4 dot of 64
        float4 sv = {0.f, 0.f, 0.f, 0.f};
        const float* s1p = &s1S[r * 272 + h * 68];
        const float* tp  = &toks[r * 544 + t * 68];
#pragma unroll
        for (int j4 = 0; j4 < 16; ++j4) {
            float4 a4 = *(const float4*)(s1p + 4 * j4);
            float4 b4 = *(const float4*)(tp + 4 * j4);
            sv.x = fmaf(a4.x, b4.x, sv.x);
            sv.y = fmaf(a4.y, b4.y, sv.y);
            sv.z = fmaf(a4.z, b4.z, sv.z);
            sv.w = fmaf(a4.w, b4.w, sv.w);
        }
        float s = (sv.x + sv.y + sv.z + sv.w) * 0.25f;
        float m = s;
        m = fmaxf(m, __shfl_xor_sync(0xffffffffu, m, 1, 8));
        m = fmaxf(m, __shfl_xor_sync(0xffffffffu, m, 2, 8));
        m = fmaxf(m, __shfl_xor_sync(0xffffffffu, m, 4, 8));
        float ex = expf(s - m);
        float den = ex;
        den += __shfl_xor_sync(0xffffffffu, den, 1, 8);
        den += __shfl_xor_sync(0xffffffffu, den, 2, 8);
        den += __shfl_xor_sync(0xffffffffu, den, 4, 8);
        float a = ex / den;
        attnS[r * 32 + lane] = a;
        float ah = a;
        ah += __shfl_xor_sync(0xffffffffu, ah, 8);
        ah += __shfl_xor_sync(0xffffffffu, ah, 16);
        float aw = fmaxf(ah * 0.25f, 1e-8f);
        float term = -aw * logf(aw);
        term += __shfl_xor_sync(0xffffffffu, term, 1, 8);
        term += __shfl_xor_sync(0xffffffffu, term, 2, 8);
        term += __shfl_xor_sync(0xffffffffu, term, 4, 8);
        if (lane == 0) out_ent[row] = term;
        __syncwarp();
        // wtok: lane owns 8 consecutive hj = lane*8 .. lane*8+7 (head hh fixed)
        float av[8];
#pragma unroll
        for (int tt = 0; tt < 8; ++tt) av[tt] = attnS[r * 32 + hh * 8 + tt];
        float4 acc0 = {0.f, 0.f, 0.f, 0.f}, acc1 = {0.f, 0.f, 0.f, 0.f};
        const float* tb = &toks[r * 544 + jb];
#pragma unroll
        for (int tt = 0; tt < 8; ++tt) {
            float4 t0 = *(const float4*)(tb + tt * 68);
            float4 t1 = *(const float4*)(tb + tt * 68 + 4);
            float av_ = av[tt];
            acc0.x = fmaf(av_, t0.x, acc0.x);
            acc0.y = fmaf(av_, t0.y, acc0.y);
            acc0.z = fmaf(av_, t0.z, acc0.z);
            acc0.w = fmaf(av_, t0.w, acc0.w);
            acc1.x = fmaf(av_, t1.x, acc1.x);
            acc1.y = fmaf(av_, t1.y, acc1.y);
            acc1.z = fmaf(av_, t1.z, acc1.z);
            acc1.w = fmaf(av_, t1.w, acc1.w);
        }
        *(float4*)&g_wtok[row * 256 + lane * 8]     = acc0;
        *(float4*)&g_wtok[row * 256 + lane * 8 + 4] = acc1;
    }
}

// ============ K4: y = wtok@G^T + cb, + remb(root) + LN + head ============
#define K4_SMEM_FLOATS 13184
#define K4_SMEM_BYTES (K4_SMEM_FLOATS * 4)

__global__ __launch_bounds__(256) void k4_out_ln_head(
    const float* __restrict__ obs,
    const float* __restrict__ Wr, const float* __restrict__ br,
    const float* __restrict__ gamma, const float* __restrict__ beta,
    const float* __restrict__ Wh1, const float* __restrict__ bh1,
    const float* __restrict__ Wh2, const float* __restrict__ bh2,
    float* __restrict__ out_ctx) {
    extern __shared__ float sm[];
    float* As = sm;                 // 2*128*20 = 5120
    float* Bs = sm + 5120;          // 2*64*20 = 2560
    float* ys = sm;                 // epi: 128*68 = 8704 (reuses As/Bs)
    float* Wh1S  = sm + 8704;       // 32*68 = 2176
    float* WrS   = sm + 10880;      // 64*12 = 768
    float* rootS = sm + 11648;      // 128*12 = 1536

    const int tid = threadIdx.x;
    const int lane = tid & 31, w = tid >> 5;
    const int row0 = blockIdx.x * 128;
    const int wm = (w & 3) * 32, wn = (w >> 2) * 32;
    const int g = lane >> 2, tig = lane & 3;

    float acc[2][4][4] = {};

    auto loadTile = [&](int s, int kt) {
        const int kb = kt * 16;
#pragma unroll
        for (int l = 0; l < 2; ++l) {
            int idx = tid + l * 256;
            int r = idx >> 2, c = (idx & 3) * 4;
            cp16((unsigned)__cvta_generic_to_shared(&As[(s * 128 + r) * 20 + c]),
                 g_wtok + (size_t)(row0 + r) * 256 + kb + c);
        }
        {
            int r = tid >> 2, c = (tid & 3) * 4;
            cp16((unsigned)__cvta_generic_to_shared(&Bs[(s * 64 + r) * 20 + c]),
                 g_G + (size_t)r * 256 + kb + c);
        }
    };

    loadTile(0, 0);
    CP_COMMIT;
    for (int kt = 0; kt < 16; ++kt) {
        CP_WAIT0;
        __syncthreads();
        if (kt + 1 < 16) {
            loadTile((kt + 1) & 1, kt + 1);
            CP_COMMIT;
        }
        const int s = kt & 1;
#pragma unroll
        for (int km = 0; km < 2; ++km) {
            unsigned a[2][4], b[4][2];
            const int k0 = km * 8 + tig;
#pragma unroll
            for (int mt = 0; mt < 2; ++mt) {
                int r = wm + mt * 16 + g;
                a[mt][0] = cvt_tf32(As[(s * 128 + r) * 20 + k0]);
                a[mt][1] = cvt_tf32(As[(s * 128 + r + 8) * 20 + k0]);
                a[mt][2] = cvt_tf32(As[(s * 128 + r) * 20 + k0 + 4]);
                a[mt][3] = cvt_tf32(As[(s * 128 + r + 8) * 20 + k0 + 4]);
            }
#pragma unroll
            for (int nt = 0; nt < 4; ++nt) {
                int n = wn + nt * 8 + g;
                b[nt][0] = cvt_tf32(Bs[(s * 64 + n) * 20 + k0]);
                b[nt][1] = cvt_tf32(Bs[(s * 64 + n) * 20 + k0 + 4]);
            }
#pragma unroll
            for (int mt = 0; mt < 2; ++mt)
#pragma unroll
                for (int nt = 0; nt < 4; ++nt) mma8(acc[mt][nt], a[mt], b[nt]);
        }
    }
    __syncthreads();   // done with As/Bs; reuse as ys

#pragma unroll
    for (int mt = 0; mt < 2; ++mt) {
#pragma unroll
        for (int nt = 0; nt < 4; ++nt) {
            int r = wm + mt * 16 + g;
            int col = wn + nt * 8 + 2 * tig;
            float c0 = g_cb[col], c1 = g_cb[col + 1];
            ys[r * 68 + col]           = acc[mt][nt][0] + c0;
            ys[r * 68 + col + 1]       = acc[mt][nt][1] + c1;
            ys[(r + 8) * 68 + col]     = acc[mt][nt][2] + c0;
            ys[(r + 8) * 68 + col + 1] = acc[mt][nt][3] + c1;
        }
    }
    for (int idx = tid; idx < 2048; idx += 256)
        Wh1S[(idx >> 6) * 68 + (idx & 63)] = Wh1[idx];
    for (int idx = tid; idx < 704; idx += 256)
        WrS[(idx / 11) * 12 + (idx % 11)] = Wr[idx];
    for (int idx = tid; idx < 1408; idx += 256) {
        int r = idx / 11, j = idx % 11;
        int col = (j < 5) ? j : (17 + j);
        rootS[r * 12 + j] = obs[(size_t)(row0 + r) * 376 + col];
    }
    __syncthreads();

    const float gm0 = gamma[lane], gm1 = gamma[lane + 32];
    const float bt0 = beta[lane],  bt1 = beta[lane + 32];
    const float br0 = br[lane],    br1 = br[lane + 32];
    const float bh1v = bh1[lane], wh2v = Wh2[lane], bh2v = bh2[0];

#pragma unroll 2
    for (int rr = 0; rr < 16; ++rr) {
        const int r = w * 16 + rr;
        const size_t row = (size_t)row0 + r;
        // remb inline
        float e0 = br0, e1 = br1;
#pragma unroll
        for (int j = 0; j < 11; ++j) {
            float rv = rootS[r * 12 + j];
            e0 = fmaf(rv, WrS[lane * 12 + j], e0);
            e1 = fmaf(rv, WrS[(lane + 32) * 12 + j], e1);
        }
        float x0 = ys[r * 68 + lane] + e0;
        float x1 = ys[r * 68 + lane + 32] + e1;
        float ssum = x0 + x1;
#pragma unroll
        for (int o = 16; o > 0; o >>= 1) ssum += __shfl_xor_sync(0xffffffffu, ssum, o);
        float mu = ssum * (1.f / 64.f);
        float d0 = x0 - mu, d1 = x1 - mu;
        float vs = d0 * d0 + d1 * d1;
#pragma unroll
        for (int o = 16; o > 0; o >>= 1) vs += __shfl_xor_sync(0xffffffffu, vs, o);
        float inv = rsqrtf(vs * (1.f / 64.f) + 1e-5f);
        float c0 = fmaf(gm0, d0 * inv, bt0);
        float c1 = fmaf(gm1, d1 * inv, bt1);
        out_ctx[row * 64 + lane] = c0;
        out_ctx[row * 64 + lane + 32] = c1;
        ys[r * 68 + lane] = c0;
        ys[r * 68 + lane + 32] = c1;
        __syncwarp();
        float4 hv = {0.f, 0.f, 0.f, 0.f};
#pragma unroll
        for (int d4 = 0; d4 < 16; ++d4) {
            float4 yv = *(const float4*)&ys[r * 68 + 4 * d4];
            float4 wv = *(const float4*)&Wh1S[lane * 68 + 4 * d4];
            hv.x = fmaf(yv.x, wv.x, hv.x);
            hv.y = fmaf(yv.y, wv.y, hv.y);
            hv.z = fmaf(yv.z, wv.z, hv.z);
            hv.w = fmaf(yv.w, wv.w, hv.w);
        }
        float v = fmaxf(hv.x + hv.y + hv.z + hv.w + bh1v, 0.f) * wh2v;
#pragma unroll
        for (int o = 16; o > 0; o >>= 1) v += __shfl_xor_sync(0xffffffffu, v, o);
        if (lane == 0) g_raw[row] = v + bh2v;
        __syncwarp();
    }
}

// ================= batch reductions =================
__global__ void k_reduce_raw() {
    __shared__ float s[256];
    int tid = threadIdx.x;
    int i = blockIdx.x * 512 + tid;
    s[tid] = g_raw[i] + g_raw[i + 256];
    __syncthreads();
    for (int o = 128; o > 0; o >>= 1) {
        if (tid < o) s[tid] += s[tid + o];
        __syncthreads();
    }
    if (tid == 0) g_part[blockIdx.x] = s[0];
}
__global__ void k_finish_raw() {
    __shared__ float s[256];
    int tid = threadIdx.x;
    s[tid] = g_part[tid];
    __syncthreads();
    for (int o = 128; o > 0; o >>= 1) {
        if (tid < o) s[tid] += s[tid + o];
        __syncthreads();
    }
    if (tid == 0) g_scalars[0] = s[0] * (1.f / (float)BATCH);
}
__global__ void k_reduce_lw() {
    __shared__ float s[256];
    int tid = threadIdx.x;
    float mean = g_scalars[0];
    int i = blockIdx.x * 512 + tid;
    s[tid] = expf(0.5f * tanhf(g_raw[i] - mean)) +
             expf(0.5f * tanhf(g_raw[i + 256] - mean));
    __syncthreads();
    for (int o = 128; o > 0; o >>= 1) {
        if (tid < o) s[tid] += s[tid + o];
        __syncthreads();
    }
    if (tid == 0) g_part[blockIdx.x] = s[0];
}
__global__ void k_finish_lw() {
    __shared__ float s[256];
    int tid = threadIdx.x;
    s[tid] = g_part[tid];
    __syncthreads();
    for (int o = 128; o > 0; o >>= 1) {
        if (tid < o) s[tid] += s[tid + o];
        __syncthreads();
    }
    if (tid == 0) g_scalars[1] = fmaxf(s[0] * (1.f / (float)BATCH), 1e-6f);
}
__global__ void k_write_lw(float* __restrict__ out_lw) {
    int i = blockIdx.x * 256 + threadIdx.x;
    float lw = expf(0.5f * tanhf(g_raw[i] - g_scalars[0]));
    out_lw[i] = lw / g_scalars[1];
}

// =====================================================================
extern "C" void kernel_launch(void* const* d_in, const int* in_sizes, int n_in,
                              void* d_out, int out_size) {
    const float* obs   = (const float*)d_in[0];
    const float* W1    = (const float*)d_in[1];
    const float* b1    = (const float*)d_in[2];
    const float* W2    = (const float*)d_in[3];
    const float* b2    = (const float*)d_in[4];
    const float* Wr    = (const float*)d_in[5];
    const float* br    = (const float*)d_in[6];
    const float* Win   = (const float*)d_in[7];
    const float* bin_  = (const float*)d_in[8];
    const float* Wout  = (const float*)d_in[9];
    const float* bout  = (const float*)d_in[10];
    const float* gamma = (const float*)d_in[11];
    const float* beta  = (const float*)d_in[12];
    const float* Wh1   = (const float*)d_in[13];
    const float* bh1   = (const float*)d_in[14];
    const float* Wh2   = (const float*)d_in[15];
    const float* bh2   = (const float*)d_in[16];

    float* out     = (float*)d_out;
    float* out_ctx = out;
    float* out_lw  = out + (size_t)BATCH * 64;
    float* out_ent = out_lw + BATCH;

    cudaFuncSetAttribute(k3a_attn, cudaFuncAttributeMaxDynamicSharedMemorySize,
                         K3A_SMEM_BYTES);
    cudaFuncSetAttribute(k4_out_ln_head, cudaFuncAttributeMaxDynamicSharedMemorySize,
                         K4_SMEM_BYTES);

    float* d_H;   cudaGetSymbolAddress((void**)&d_H, g_H);
    float* d_tok; cudaGetSymbolAddress((void**)&d_tok, g_tok);

    k0_fold<<<8, 256>>>(Wr, br, Win, bin_, Wout, bout);
    gemm_tf32<20, true, true, 376, 308, 256>
        <<<dim3(BATCH / 128, 2), 256>>>(obs, W1, b1, d_H);
    gemm_tf32<16, false, false, 0, 256, 512>
        <<<dim3(BATCH / 128, 4), 256>>>(d_H, W2, b2, d_tok);
    k3a_attn<<<BATCH / 16, 256, K3A_SMEM_BYTES>>>(obs, out_ent);
    k4_out_ln_head<<<BATCH / 128, 256, K4_SMEM_BYTES>>>(
        obs, Wr, br, gamma, beta, Wh1, bh1, Wh2, bh2, out_ctx);
    k_reduce_raw<<<256, 256>>>();
    k_finish_raw<<<1, 256>>>();
    k_reduce_lw<<<256, 256>>>();
    k_finish_lw<<<1, 256>>>();
    k_write_lw<<<BATCH / 256, 256>>>(out_lw);
}

// round 8
// speedup vs baseline: 5.4220x; 1.0491x over previous
#include <cuda_runtime.h>
#include <math.h>

#define BATCH 131072

__device__ float g_H[(size_t)BATCH * 256];
__device__ float g_tok[(size_t)BATCH * 512];
__device__ float g_wtok[(size_t)BATCH * 256];
__device__ float g_raw[BATCH];
__device__ float g_part[256];
__device__ float g_scalars[2];
// folded weights
__device__ float g_A1T[12 * 256];   // [t][hj]
__device__ float g_c1[256];
__device__ float g_G[64 * 256];     // [e][hj]
__device__ float g_cb[64];

// ---------------- tf32 / cp.async helpers ----------------
__device__ __forceinline__ unsigned cvt_tf32(float x) {
    unsigned u;
    asm("cvt.rna.tf32.f32 %0, %1;" : "=r"(u) : "f"(x));
    return u;
}
__device__ __forceinline__ void cp4(unsigned dst, const float* src, unsigned sz) {
    asm volatile("cp.async.ca.shared.global [%0], [%1], 4, %2;" ::
                 "r"(dst), "l"(src), "r"(sz));
}
__device__ __forceinline__ void cp16(unsigned dst, const float* src) {
    asm volatile("cp.async.cg.shared.global [%0], [%1], 16;" ::
                 "r"(dst), "l"(src));
}
__device__ __forceinline__ void cp16z(unsigned dst, const float* src, unsigned sz) {
    asm volatile("cp.async.cg.shared.global [%0], [%1], 16, %2;" ::
                 "r"(dst), "l"(src), "r"(sz));
}
#define CP_COMMIT asm volatile("cp.async.commit_group;")
#define CP_WAIT0  asm volatile("cp.async.wait_group 0;")

__device__ __forceinline__ void mma8(float* d, const unsigned* a, const unsigned* b) {
    asm volatile(
        "mma.sync.aligned.m16n8k8.row.col.f32.tf32.tf32.f32 "
        "{%0,%1,%2,%3}, {%4,%5,%6,%7}, {%8,%9}, {%0,%1,%2,%3};"
        : "+f"(d[0]), "+f"(d[1]), "+f"(d[2]), "+f"(d[3])
        : "r"(a[0]), "r"(a[1]), "r"(a[2]), "r"(a[3]), "r"(b[0]), "r"(b[1]));
}

// ============ K0: fold precompute ============
__global__ __launch_bounds__(256) void k0_fold(
    const float* __restrict__ Wr, const float* __restrict__ br,
    const float* __restrict__ Win, const float* __restrict__ bin_,
    const float* __restrict__ Wout, const float* __restrict__ bout) {
    __shared__ float QW[64 * 12];
    __shared__ float qsS[64];
    const int tid = threadIdx.x, bx = blockIdx.x;

    if (bx == 0) {
        for (int idx = tid; idx < 704; idx += 256) {
            int e = idx / 11, t = idx % 11;
            float acc = 0.f;
            for (int d = 0; d < 64; ++d) acc = fmaf(Win[e * 64 + d], Wr[d * 11 + t], acc);
            QW[e * 12 + t] = acc;
        }
        for (int idx = tid; idx < 64; idx += 256) {
            float acc = bin_[idx];
            for (int d = 0; d < 64; ++d) acc = fmaf(Win[idx * 64 + d], br[d], acc);
            qsS[idx] = acc;
        }
        __syncthreads();
        for (int idx = tid; idx < 2816; idx += 256) {
            int hj = idx / 11, t = idx % 11;
            int h = hj >> 6, j = hj & 63;
            float acc = 0.f;
            for (int e = 0; e < 16; ++e) {
                int x = h * 16 + e;
                acc = fmaf(Win[4096 + x * 64 + j], QW[x * 12 + t], acc);
            }
            g_A1T[t * 256 + hj] = acc;
        }
        for (int idx = tid; idx < 256; idx += 256) {
            int h = idx >> 6, j = idx & 63;
            float acc = 0.f;
            for (int e = 0; e < 16; ++e) {
                int x = h * 16 + e;
                acc = fmaf(Win[4096 + x * 64 + j], qsS[x], acc);
            }
            g_c1[idx] = acc;
        }
        for (int idx = tid; idx < 64; idx += 256) {
            float acc = bout[idx];
            for (int d = 0; d < 64; ++d) acc = fmaf(Wout[idx * 64 + d], bin_[128 + d], acc);
            g_cb[idx] = acc;
        }
    }
    for (int idx = tid; idx < 2048; idx += 256) {
        int e = bx * 8 + (idx >> 8);
        int hj = idx & 255, h = hj >> 6, j = hj & 63;
        float acc = 0.f;
        for (int d = 0; d < 16; ++d)
            acc = fmaf(Wout[e * 64 + h * 16 + d], Win[8192 + (h * 16 + d) * 64 + j], acc);
        g_G[e * 256 + hj] = acc;
    }
}

// ============ tf32 tile GEMM 128x128 ============
template <int KT, bool GATHER, bool RELU, int LDA, int KROW, int LDC>
__global__ __launch_bounds__(256) void gemm_tf32(const float* __restrict__ A,
                                                 const float* __restrict__ W,
                                                 const float* __restrict__ bias,
                                                 float* __restrict__ C) {
    __shared__ float As[2][128][20];
    __shared__ float Bs[2][128][20];
    const int tid = threadIdx.x;
    const int lane = tid & 31, w = tid >> 5;
    const int row0 = blockIdx.x * 128, n0 = blockIdx.y * 128;
    const int wm = (w & 1) * 64, wn = (w >> 1) * 32;
    const int g = lane >> 2, tig = lane & 3;

    float acc[4][4][4] = {};

    auto loadTile = [&](int s, int kt) {
        const int kb = kt * 16;
        if (GATHER) {
#pragma unroll
            for (int l = 0; l < 8; ++l) {
                int idx = tid + l * 256;
                int r = idx >> 4, kk = idx & 15;
                int k = kb + kk;
                int col = (k < 224) ? (45 + k) : (68 + k);
                const float* src = A + (size_t)(row0 + r) * LDA + ((k < KROW) ? col : 0);
                cp4((unsigned)__cvta_generic_to_shared(&As[s][r][kk]), src,
                    (k < KROW) ? 4u : 0u);
            }
#pragma unroll
            for (int l = 0; l < 2; ++l) {
                int idx = tid + l * 256;
                int n = idx >> 2, c = (idx & 3) * 4;
                int k = kb + c;
                cp16z((unsigned)__cvta_generic_to_shared(&Bs[s][n][c]),
                      W + (size_t)(n0 + n) * KROW + ((k < KROW) ? k : 0),
                      (k + 4 <= KROW) ? 16u : 0u);
            }
        } else {
#pragma unroll
            for (int l = 0; l < 2; ++l) {
                int idx = tid + l * 256;
                int r = idx >> 2, c = (idx & 3) * 4;
                cp16((unsigned)__cvta_generic_to_shared(&As[s][r][c]),
                     A + (size_t)(row0 + r) * KROW + kb + c);
            }
#pragma unroll
            for (int l = 0; l < 2; ++l) {
                int idx = tid + l * 256;
                int n = idx >> 2, c = (idx & 3) * 4;
                cp16((unsigned)__cvta_generic_to_shared(&Bs[s][n][c]),
                     W + (size_t)(n0 + n) * KROW + kb + c);
            }
        }
    };

    loadTile(0, 0);
    CP_COMMIT;

    for (int kt = 0; kt < KT; ++kt) {
        CP_WAIT0;
        __syncthreads();
        if (kt + 1 < KT) {
            loadTile((kt + 1) & 1, kt + 1);
            CP_COMMIT;
        }
        const int s = kt & 1;
#pragma unroll
        for (int km = 0; km < 2; ++km) {
            unsigned a[4][4], b[4][2];
            const int k0 = km * 8 + tig;
#pragma unroll
            for (int mt = 0; mt < 4; ++mt) {
                int r = wm + mt * 16 + g;
                a[mt][0] = cvt_tf32(As[s][r][k0]);
                a[mt][1] = cvt_tf32(As[s][r + 8][k0]);
                a[mt][2] = cvt_tf32(As[s][r][k0 + 4]);
                a[mt][3] = cvt_tf32(As[s][r + 8][k0 + 4]);
            }
#pragma unroll
            for (int nt = 0; nt < 4; ++nt) {
                int n = wn + nt * 8 + g;
                b[nt][0] = cvt_tf32(Bs[s][n][k0]);
                b[nt][1] = cvt_tf32(Bs[s][n][k0 + 4]);
            }
#pragma unroll
            for (int mt = 0; mt < 4; ++mt)
#pragma unroll
                for (int nt = 0; nt < 4; ++nt) mma8(acc[mt][nt], a[mt], b[nt]);
        }
    }

#pragma unroll
    for (int mt = 0; mt < 4; ++mt) {
#pragma unroll
        for (int nt = 0; nt < 4; ++nt) {
            int row = row0 + wm + mt * 16 + g;
            int col = n0 + wn + nt * 8 + 2 * tig;
            float b0 = __ldg(bias + col), b1 = __ldg(bias + col + 1);
            float v0 = acc[mt][nt][0] + b0, v1 = acc[mt][nt][1] + b1;
            float v2 = acc[mt][nt][2] + b0, v3 = acc[mt][nt][3] + b1;
            if (RELU) {
                v0 = fmaxf(v0, 0.f); v1 = fmaxf(v1, 0.f);
                v2 = fmaxf(v2, 0.f); v3 = fmaxf(v3, 0.f);
            }
            float2 p0 = {v0, v1}, p1 = {v2, v3};
            *(float2*)&C[(size_t)row * LDC + col] = p0;
            *(float2*)&C[(size_t)(row + 8) * LDC + col] = p1;
        }
    }
}

// ============ K3a: block-coop s1, scores, softmax, entropy, wtok ============
#define K3A_SMEM_FLOATS 14016
#define K3A_SMEM_BYTES (K3A_SMEM_FLOATS * 4)

__global__ __launch_bounds__(256) void k3a_attn(const float* __restrict__ obs,
                                                float* __restrict__ out_ent) {
    extern __shared__ float sm[];
    float* toks  = sm;              // 16*544 = 8704
    float* s1S   = toks + 8704;     // 16*272 = 4352
    float* rootS = s1S + 4352;      // 192
    float* attnS = rootS + 192;     // 512

    const int tid = threadIdx.x;
    const int lane = tid & 31, w = tid >> 5;
    const int row0 = blockIdx.x * 16;

    // toks via cp.async (single-path staging)
    {
        const float* src = g_tok + (size_t)row0 * 512;
#pragma unroll
        for (int l = 0; l < 8; ++l) {
            int idx = (tid + l * 256) * 4;
            int r = idx >> 9, c = idx & 511;
            cp16((unsigned)__cvta_generic_to_shared(
                     &toks[r * 544 + (c >> 6) * 68 + (c & 63)]),
                 src + (size_t)r * 512 + c);
        }
    }
    CP_COMMIT;
    for (int idx = tid; idx < 176; idx += 256) {
        int r = idx / 11, j = idx % 11;
        int col = (j < 5) ? j : (17 + j);
        rootS[r * 12 + j] = obs[(size_t)(row0 + r) * 376 + col];
    }
    // A1T column hj=tid cached in registers (gmem, coalesced)
    float a1[11];
#pragma unroll
    for (int t = 0; t < 11; ++t) a1[t] = g_A1T[t * 256 + tid];
    const float c1v = g_c1[tid];
    CP_WAIT0;
    __syncthreads();

    // block-cooperative s1 for all 16 rows: tid owns hj=tid
    {
        const int dst = (tid >> 6) * 68 + (tid & 63);
#pragma unroll
        for (int r = 0; r < 16; ++r) {
            float acc = c1v;
#pragma unroll
            for (int t = 0; t < 11; ++t) acc = fmaf(rootS[r * 12 + t], a1[t], acc);
            s1S[r * 272 + dst] = acc;
        }
    }
    __syncthreads();

    const int h = lane >> 3, t = lane & 7;
    const int hh = lane >> 3;          // head for wtok (j-block = lane*8)
    const int jb = (lane * 8) & 63;    // j offset within token
#pragma unroll
    for (int rr = 0; rr < 2; ++rr) {
        const int r = w * 2 + rr;
        const size_t row = (size_t)row0 + r;
        // scores: float4 dot of 64 (s1 8-way, tok 4-way smem broadcast)
        float4 sv = {0.f, 0.f, 0.f, 0.f};
        const float* s1p = &s1S[r * 272 + h * 68];
        const float* tp  = &toks[r * 544 + t * 68];
#pragma unroll
        for (int j4 = 0; j4 < 16; ++j4) {
            float4 a4 = *(const float4*)(s1p + 4 * j4);
            float4 b4 = *(const float4*)(tp + 4 * j4);
            sv.x = fmaf(a4.x, b4.x, sv.x);
            sv.y = fmaf(a4.y, b4.y, sv.y);
            sv.z = fmaf(a4.z, b4.z, sv.z);
            sv.w = fmaf(a4.w, b4.w, sv.w);
        }
        float s = (sv.x + sv.y + sv.z + sv.w) * 0.25f;
        float m = s;
        m = fmaxf(m, __shfl_xor_sync(0xffffffffu, m, 1, 8));
        m = fmaxf(m, __shfl_xor_sync(0xffffffffu, m, 2, 8));
        m = fmaxf(m, __shfl_xor_sync(0xffffffffu, m, 4, 8));
        float ex = expf(s - m);
        float den = ex;
        den += __shfl_xor_sync(0xffffffffu, den, 1, 8);
        den += __shfl_xor_sync(0xffffffffu, den, 2, 8);
        den += __shfl_xor_sync(0xffffffffu, den, 4, 8);
        float a = ex / den;
        attnS[r * 32 + lane] = a;
        float ah = a;
        ah += __shfl_xor_sync(0xffffffffu, ah, 8);
        ah += __shfl_xor_sync(0xffffffffu, ah, 16);
        float aw = fmaxf(ah * 0.25f, 1e-8f);
        float term = -aw * logf(aw);
        term += __shfl_xor_sync(0xffffffffu, term, 1, 8);
        term += __shfl_xor_sync(0xffffffffu, term, 2, 8);
        term += __shfl_xor_sync(0xffffffffu, term, 4, 8);
        if (lane == 0) out_ent[row] = term;
        __syncwarp();
        // wtok: lane owns 8 consecutive hj = lane*8 .. lane*8+7 (head hh fixed)
        float av[8];
#pragma unroll
        for (int tt = 0; tt < 8; ++tt) av[tt] = attnS[r * 32 + hh * 8 + tt];
        float4 acc0 = {0.f, 0.f, 0.f, 0.f}, acc1 = {0.f, 0.f, 0.f, 0.f};
        const float* tb = &toks[r * 544 + jb];
#pragma unroll
        for (int tt = 0; tt < 8; ++tt) {
            float4 t0 = *(const float4*)(tb + tt * 68);
            float4 t1 = *(const float4*)(tb + tt * 68 + 4);
            float av_ = av[tt];
            acc0.x = fmaf(av_, t0.x, acc0.x);
            acc0.y = fmaf(av_, t0.y, acc0.y);
            acc0.z = fmaf(av_, t0.z, acc0.z);
            acc0.w = fmaf(av_, t0.w, acc0.w);
            acc1.x = fmaf(av_, t1.x, acc1.x);
            acc1.y = fmaf(av_, t1.y, acc1.y);
            acc1.z = fmaf(av_, t1.z, acc1.z);
            acc1.w = fmaf(av_, t1.w, acc1.w);
        }
        *(float4*)&g_wtok[row * 256 + lane * 8]     = acc0;
        *(float4*)&g_wtok[row * 256 + lane * 8 + 4] = acc1;
    }
}

// ============ K4: y = wtok@G^T + cb, + remb(root) + LN + head ============
#define K4_SMEM_FLOATS 13184
#define K4_SMEM_BYTES (K4_SMEM_FLOATS * 4)

__global__ __launch_bounds__(256) void k4_out_ln_head(
    const float* __restrict__ obs,
    const float* __restrict__ Wr, const float* __restrict__ br,
    const float* __restrict__ gamma, const float* __restrict__ beta,
    const float* __restrict__ Wh1, const float* __restrict__ bh1,
    const float* __restrict__ Wh2, const float* __restrict__ bh2,
    float* __restrict__ out_ctx) {
    extern __shared__ float sm[];
    float* As = sm;                 // 2*128*20 = 5120
    float* Bs = sm + 5120;          // 2*64*20 = 2560
    float* ys = sm;                 // epi: 128*68 = 8704 (reuses As/Bs)
    float* Wh1S  = sm + 8704;       // 32*68 = 2176
    float* WrS   = sm + 10880;      // 64*12 = 768
    float* rootS = sm + 11648;      // 128*12 = 1536

    const int tid = threadIdx.x;
    const int lane = tid & 31, w = tid >> 5;
    const int row0 = blockIdx.x * 128;
    const int wm = (w & 3) * 32, wn = (w >> 2) * 32;
    const int g = lane >> 2, tig = lane & 3;

    float acc[2][4][4] = {};

    auto loadTile = [&](int s, int kt) {
        const int kb = kt * 16;
#pragma unroll
        for (int l = 0; l < 2; ++l) {
            int idx = tid + l * 256;
            int r = idx >> 2, c = (idx & 3) * 4;
            cp16((unsigned)__cvta_generic_to_shared(&As[(s * 128 + r) * 20 + c]),
                 g_wtok + (size_t)(row0 + r) * 256 + kb + c);
        }
        {
            int r = tid >> 2, c = (tid & 3) * 4;
            cp16((unsigned)__cvta_generic_to_shared(&Bs[(s * 64 + r) * 20 + c]),
                 g_G + (size_t)r * 256 + kb + c);
        }
    };

    loadTile(0, 0);
    CP_COMMIT;
    for (int kt = 0; kt < 16; ++kt) {
        CP_WAIT0;
        __syncthreads();
        if (kt + 1 < 16) {
            loadTile((kt + 1) & 1, kt + 1);
            CP_COMMIT;
        }
        const int s = kt & 1;
#pragma unroll
        for (int km = 0; km < 2; ++km) {
            unsigned a[2][4], b[4][2];
            const int k0 = km * 8 + tig;
#pragma unroll
            for (int mt = 0; mt < 2; ++mt) {
                int r = wm + mt * 16 + g;
                a[mt][0] = cvt_tf32(As[(s * 128 + r) * 20 + k0]);
                a[mt][1] = cvt_tf32(As[(s * 128 + r + 8) * 20 + k0]);
                a[mt][2] = cvt_tf32(As[(s * 128 + r) * 20 + k0 + 4]);
                a[mt][3] = cvt_tf32(As[(s * 128 + r + 8) * 20 + k0 + 4]);
            }
#pragma unroll
            for (int nt = 0; nt < 4; ++nt) {
                int n = wn + nt * 8 + g;
                b[nt][0] = cvt_tf32(Bs[(s * 64 + n) * 20 + k0]);
                b[nt][1] = cvt_tf32(Bs[(s * 64 + n) * 20 + k0 + 4]);
            }
#pragma unroll
            for (int mt = 0; mt < 2; ++mt)
#pragma unroll
                for (int nt = 0; nt < 4; ++nt) mma8(acc[mt][nt], a[mt], b[nt]);
        }
    }
    __syncthreads();   // done with As/Bs; reuse as ys

#pragma unroll
    for (int mt = 0; mt < 2; ++mt) {
#pragma unroll
        for (int nt = 0; nt < 4; ++nt) {
            int r = wm + mt * 16 + g;
            int col = wn + nt * 8 + 2 * tig;
            float c0 = g_cb[col], c1 = g_cb[col + 1];
            ys[r * 68 + col]           = acc[mt][nt][0] + c0;
            ys[r * 68 + col + 1]       = acc[mt][nt][1] + c1;
            ys[(r + 8) * 68 + col]     = acc[mt][nt][2] + c0;
            ys[(r + 8) * 68 + col + 1] = acc[mt][nt][3] + c1;
        }
    }
    for (int idx = tid; idx < 2048; idx += 256)
        Wh1S[(idx >> 6) * 68 + (idx & 63)] = Wh1[idx];
    for (int idx = tid; idx < 704; idx += 256)
        WrS[(idx / 11) * 12 + (idx % 11)] = Wr[idx];
    for (int idx = tid; idx < 1408; idx += 256) {
        int r = idx / 11, j = idx % 11;
        int col = (j < 5) ? j : (17 + j);
        rootS[r * 12 + j] = obs[(size_t)(row0 + r) * 376 + col];
    }
    __syncthreads();

    const float gm0 = gamma[lane], gm1 = gamma[lane + 32];
    const float bt0 = beta[lane],  bt1 = beta[lane + 32];
    const float br0 = br[lane],    br1 = br[lane + 32];
    const float bh1v = bh1[lane], wh2v = Wh2[lane], bh2v = bh2[0];

#pragma unroll 2
    for (int rr = 0; rr < 16; ++rr) {
        const int r = w * 16 + rr;
        const size_t row = (size_t)row0 + r;
        float e0 = br0, e1 = br1;
#pragma unroll
        for (int j = 0; j < 11; ++j) {
            float rv = rootS[r * 12 + j];
            e0 = fmaf(rv, WrS[lane * 12 + j], e0);
            e1 = fmaf(rv, WrS[(lane + 32) * 12 + j], e1);
        }
        float x0 = ys[r * 68 + lane] + e0;
        float x1 = ys[r * 68 + lane + 32] + e1;
        float ssum = x0 + x1;
#pragma unroll
        for (int o = 16; o > 0; o >>= 1) ssum += __shfl_xor_sync(0xffffffffu, ssum, o);
        float mu = ssum * (1.f / 64.f);
        float d0 = x0 - mu, d1 = x1 - mu;
        float vs = d0 * d0 + d1 * d1;
#pragma unroll
        for (int o = 16; o > 0; o >>= 1) vs += __shfl_xor_sync(0xffffffffu, vs, o);
        float inv = rsqrtf(vs * (1.f / 64.f) + 1e-5f);
        float c0 = fmaf(gm0, d0 * inv, bt0);
        float c1 = fmaf(gm1, d1 * inv, bt1);
        out_ctx[row * 64 + lane] = c0;
        out_ctx[row * 64 + lane + 32] = c1;
        ys[r * 68 + lane] = c0;
        ys[r * 68 + lane + 32] = c1;
        __syncwarp();
        float4 hv = {0.f, 0.f, 0.f, 0.f};
#pragma unroll
        for (int d4 = 0; d4 < 16; ++d4) {
            float4 yv = *(const float4*)&ys[r * 68 + 4 * d4];
            float4 wv = *(const float4*)&Wh1S[lane * 68 + 4 * d4];
            hv.x = fmaf(yv.x, wv.x, hv.x);
            hv.y = fmaf(yv.y, wv.y, hv.y);
            hv.z = fmaf(yv.z, wv.z, hv.z);
            hv.w = fmaf(yv.w, wv.w, hv.w);
        }
        float v = fmaxf(hv.x + hv.y + hv.z + hv.w + bh1v, 0.f) * wh2v;
#pragma unroll
        for (int o = 16; o > 0; o >>= 1) v += __shfl_xor_sync(0xffffffffu, v, o);
        if (lane == 0) g_raw[row] = v + bh2v;
        __syncwarp();
    }
}

// ================= batch reductions =================
__global__ void k_reduce_raw() {
    __shared__ float s[256];
    int tid = threadIdx.x;
    int i = blockIdx.x * 512 + tid;
    s[tid] = g_raw[i] + g_raw[i + 256];
    __syncthreads();
    for (int o = 128; o > 0; o >>= 1) {
        if (tid < o) s[tid] += s[tid + o];
        __syncthreads();
    }
    if (tid == 0) g_part[blockIdx.x] = s[0];
}
__global__ void k_finish_raw() {
    __shared__ float s[256];
    int tid = threadIdx.x;
    s[tid] = g_part[tid];
    __syncthreads();
    for (int o = 128; o > 0; o >>= 1) {
        if (tid < o) s[tid] += s[tid + o];
        __syncthreads();
    }
    if (tid == 0) g_scalars[0] = s[0] * (1.f / (float)BATCH);
}
__global__ void k_reduce_lw() {
    __shared__ float s[256];
    int tid = threadIdx.x;
    float mean = g_scalars[0];
    int i = blockIdx.x * 512 + tid;
    s[tid] = expf(0.5f * tanhf(g_raw[i] - mean)) +
             expf(0.5f * tanhf(g_raw[i + 256] - mean));
    __syncthreads();
    for (int o = 128; o > 0; o >>= 1) {
        if (tid < o) s[tid] += s[tid + o];
        __syncthreads();
    }
    if (tid == 0) g_part[blockIdx.x] = s[0];
}
__global__ void k_finish_lw() {
    __shared__ float s[256];
    int tid = threadIdx.x;
    s[tid] = g_part[tid];
    __syncthreads();
    for (int o = 128; o > 0; o >>= 1) {
        if (tid < o) s[tid] += s[tid + o];
        __syncthreads();
    }
    if (tid == 0) g_scalars[1] = fmaxf(s[0] * (1.f / (float)BATCH), 1e-6f);
}
__global__ void k_write_lw(float* __restrict__ out_lw) {
    int i = blockIdx.x * 256 + threadIdx.x;
    float lw = expf(0.5f * tanhf(g_raw[i] - g_scalars[0]));
    out_lw[i] = lw / g_scalars[1];
}

// =====================================================================
extern "C" void kernel_launch(void* const* d_in, const int* in_sizes, int n_in,
                              void* d_out, int out_size) {
    const float* obs   = (const float*)d_in[0];
    const float* W1    = (const float*)d_in[1];
    const float* b1    = (const float*)d_in[2];
    const float* W2    = (const float*)d_in[3];
    const float* b2    = (const float*)d_in[4];
    const float* Wr    = (const float*)d_in[5];
    const float* br    = (const float*)d_in[6];
    const float* Win   = (const float*)d_in[7];
    const float* bin_  = (const float*)d_in[8];
    const float* Wout  = (const float*)d_in[9];
    const float* bout  = (const float*)d_in[10];
    const float* gamma = (const float*)d_in[11];
    const float* beta  = (const float*)d_in[12];
    const float* Wh1   = (const float*)d_in[13];
    const float* bh1   = (const float*)d_in[14];
    const float* Wh2   = (const float*)d_in[15];
    const float* bh2   = (const float*)d_in[16];

    float* out     = (float*)d_out;
    float* out_ctx = out;
    float* out_lw  = out + (size_t)BATCH * 64;
    float* out_ent = out_lw + BATCH;

    cudaFuncSetAttribute(k3a_attn, cudaFuncAttributeMaxDynamicSharedMemorySize,
                         K3A_SMEM_BYTES);
    cudaFuncSetAttribute(k4_out_ln_head, cudaFuncAttributeMaxDynamicSharedMemorySize,
                         K4_SMEM_BYTES);

    float* d_H;   cudaGetSymbolAddress((void**)&d_H, g_H);
    float* d_tok; cudaGetSymbolAddress((void**)&d_tok, g_tok);

    k0_fold<<<8, 256>>>(Wr, br, Win, bin_, Wout, bout);
    gemm_tf32<20, true, true, 376, 308, 256>
        <<<dim3(BATCH / 128, 2), 256>>>(obs, W1, b1, d_H);
    gemm_tf32<16, false, false, 0, 256, 512>
        <<<dim3(BATCH / 128, 4), 256>>>(d_H, W2, b2, d_tok);
    k3a_attn<<<BATCH / 16, 256, K3A_SMEM_BYTES>>>(obs, out_ent);
    k4_out_ln_head<<<BATCH / 128, 256, K4_SMEM_BYTES>>>(
        obs, Wr, br, gamma, beta, Wh1, bh1, Wh2, bh2, out_ctx);
    k_reduce_raw<<<256, 256>>>();
    k_finish_raw<<<1, 256>>>();
    k_reduce_lw<<<256, 256>>>();
    k_finish_lw<<<1, 256>>>();
    k_write_lw<<<BATCH / 256, 256>>>(out_lw);
}

// round 9
// speedup vs baseline: 6.5137x; 1.2013x over previous
#include <cuda_runtime.h>
#include <cuda_bf16.h>
#include <math.h>

#define BATCH 131072

__device__ __nv_bfloat16 g_Hb[(size_t)BATCH * 256];
__device__ float g_tok[(size_t)BATCH * 512];
__device__ __nv_bfloat16 g_wtokb[(size_t)BATCH * 256];
__device__ float g_raw[BATCH];
__device__ float g_part[256];
__device__ float g_scalars[2];
// folded weights
__device__ float g_A1T[12 * 256];           // [t][hj]
__device__ float g_c1[256];
__device__ __nv_bfloat16 g_Gb[64 * 256];    // [e][hj] bf16
__device__ float g_cb[64];
__device__ __nv_bfloat16 g_W2b[512 * 256];

// ---------------- helpers ----------------
__device__ __forceinline__ unsigned cvt_tf32(float x) {
    unsigned u;
    asm("cvt.rna.tf32.f32 %0, %1;" : "=r"(u) : "f"(x));
    return u;
}
__device__ __forceinline__ void cp4(unsigned dst, const void* src, unsigned sz) {
    asm volatile("cp.async.ca.shared.global [%0], [%1], 4, %2;" ::
                 "r"(dst), "l"(src), "r"(sz));
}
__device__ __forceinline__ void cp16(unsigned dst, const void* src) {
    asm volatile("cp.async.cg.shared.global [%0], [%1], 16;" ::
                 "r"(dst), "l"(src));
}
__device__ __forceinline__ void cp16z(unsigned dst, const void* src, unsigned sz) {
    asm volatile("cp.async.cg.shared.global [%0], [%1], 16, %2;" ::
                 "r"(dst), "l"(src), "r"(sz));
}
#define CP_COMMIT asm volatile("cp.async.commit_group;")
#define CP_WAIT0  asm volatile("cp.async.wait_group 0;")

__device__ __forceinline__ void mma8(float* d, const unsigned* a, const unsigned* b) {
    asm volatile(
        "mma.sync.aligned.m16n8k8.row.col.f32.tf32.tf32.f32 "
        "{%0,%1,%2,%3}, {%4,%5,%6,%7}, {%8,%9}, {%0,%1,%2,%3};"
        : "+f"(d[0]), "+f"(d[1]), "+f"(d[2]), "+f"(d[3])
        : "r"(a[0]), "r"(a[1]), "r"(a[2]), "r"(a[3]), "r"(b[0]), "r"(b[1]));
}
__device__ __forceinline__ void mma16(float* d, const unsigned* a, const unsigned* b) {
    asm volatile(
        "mma.sync.aligned.m16n8k16.row.col.f32.bf16.bf16.f32 "
        "{%0,%1,%2,%3}, {%4,%5,%6,%7}, {%8,%9}, {%0,%1,%2,%3};"
        : "+f"(d[0]), "+f"(d[1]), "+f"(d[2]), "+f"(d[3])
        : "r"(a[0]), "r"(a[1]), "r"(a[2]), "r"(a[3]), "r"(b[0]), "r"(b[1]));
}

// ============ K0: fold precompute + bf16 weight conversion ============
__global__ __launch_bounds__(256) void k0_fold(
    const float* __restrict__ Wr, const float* __restrict__ br,
    const float* __restrict__ Win, const float* __restrict__ bin_,
    const float* __restrict__ Wout, const float* __restrict__ bout,
    const float* __restrict__ W2) {
    __shared__ float QW[64 * 12];
    __shared__ float qsS[64];
    const int tid = threadIdx.x, bx = blockIdx.x;

    if (bx == 0) {
        for (int idx = tid; idx < 704; idx += 256) {
            int e = idx / 11, t = idx % 11;
            float acc = 0.f;
            for (int d = 0; d < 64; ++d) acc = fmaf(Win[e * 64 + d], Wr[d * 11 + t], acc);
            QW[e * 12 + t] = acc;
        }
        for (int idx = tid; idx < 64; idx += 256) {
            float acc = bin_[idx];
            for (int d = 0; d < 64; ++d) acc = fmaf(Win[idx * 64 + d], br[d], acc);
            qsS[idx] = acc;
        }
        __syncthreads();
        for (int idx = tid; idx < 2816; idx += 256) {
            int hj = idx / 11, t = idx % 11;
            int h = hj >> 6, j = hj & 63;
            float acc = 0.f;
            for (int e = 0; e < 16; ++e) {
                int x = h * 16 + e;
                acc = fmaf(Win[4096 + x * 64 + j], QW[x * 12 + t], acc);
            }
            g_A1T[t * 256 + hj] = acc;
        }
        for (int idx = tid; idx < 256; idx += 256) {
            int h = idx >> 6, j = idx & 63;
            float acc = 0.f;
            for (int e = 0; e < 16; ++e) {
                int x = h * 16 + e;
                acc = fmaf(Win[4096 + x * 64 + j], qsS[x], acc);
            }
            g_c1[idx] = acc;
        }
        for (int idx = tid; idx < 64; idx += 256) {
            float acc = bout[idx];
            for (int d = 0; d < 64; ++d) acc = fmaf(Wout[idx * 64 + d], bin_[128 + d], acc);
            g_cb[idx] = acc;
        }
    }
    // G (bf16) : rows e in [bx*8, bx*8+8)
    for (int idx = tid; idx < 2048; idx += 256) {
        int e = bx * 8 + (idx >> 8);
        int hj = idx & 255, h = hj >> 6, j = hj & 63;
        float acc = 0.f;
        for (int d = 0; d < 16; ++d)
            acc = fmaf(Wout[e * 64 + h * 16 + d], Win[8192 + (h * 16 + d) * 64 + j], acc);
        g_Gb[e * 256 + hj] = __float2bfloat16(acc);
    }
    // W2 -> bf16 (131072 elems over 8 blocks)
    for (int idx = bx * 16384 + tid; idx < (bx + 1) * 16384; idx += 256)
        g_W2b[idx] = __float2bfloat16(W2[idx]);
}

// ============ K1: tf32 gather GEMM, bf16 output H ============
__global__ __launch_bounds__(256) void k1_gemm(const float* __restrict__ A,
                                               const float* __restrict__ W,
                                               const float* __restrict__ bias) {
    __shared__ float As[2][128][20];
    __shared__ float Bs[2][128][20];
    const int tid = threadIdx.x;
    const int lane = tid & 31, w = tid >> 5;
    const int row0 = blockIdx.x * 128, n0 = blockIdx.y * 128;
    const int wm = (w & 1) * 64, wn = (w >> 1) * 32;
    const int g = lane >> 2, tig = lane & 3;
    const int LDA = 376, KROW = 308;

    float acc[4][4][4] = {};

    auto loadTile = [&](int s, int kt) {
        const int kb = kt * 16;
#pragma unroll
        for (int l = 0; l < 8; ++l) {
            int idx = tid + l * 256;
            int r = idx >> 4, kk = idx & 15;
            int k = kb + kk;
            int col = (k < 224) ? (45 + k) : (68 + k);
            const float* src = A + (size_t)(row0 + r) * LDA + ((k < KROW) ? col : 0);
            cp4((unsigned)__cvta_generic_to_shared(&As[s][r][kk]), src,
                (k < KROW) ? 4u : 0u);
        }
#pragma unroll
        for (int l = 0; l < 2; ++l) {
            int idx = tid + l * 256;
            int n = idx >> 2, c = (idx & 3) * 4;
            int k = kb + c;
            cp16z((unsigned)__cvta_generic_to_shared(&Bs[s][n][c]),
                  W + (size_t)(n0 + n) * KROW + ((k < KROW) ? k : 0),
                  (k + 4 <= KROW) ? 16u : 0u);
        }
    };

    loadTile(0, 0);
    CP_COMMIT;

    for (int kt = 0; kt < 20; ++kt) {
        CP_WAIT0;
        __syncthreads();
        if (kt + 1 < 20) {
            loadTile((kt + 1) & 1, kt + 1);
            CP_COMMIT;
        }
        const int s = kt & 1;
#pragma unroll
        for (int km = 0; km < 2; ++km) {
            unsigned a[4][4], b[4][2];
            const int k0 = km * 8 + tig;
#pragma unroll
            for (int mt = 0; mt < 4; ++mt) {
                int r = wm + mt * 16 + g;
                a[mt][0] = cvt_tf32(As[s][r][k0]);
                a[mt][1] = cvt_tf32(As[s][r + 8][k0]);
                a[mt][2] = cvt_tf32(As[s][r][k0 + 4]);
                a[mt][3] = cvt_tf32(As[s][r + 8][k0 + 4]);
            }
#pragma unroll
            for (int nt = 0; nt < 4; ++nt) {
                int n = wn + nt * 8 + g;
                b[nt][0] = cvt_tf32(Bs[s][n][k0]);
                b[nt][1] = cvt_tf32(Bs[s][n][k0 + 4]);
            }
#pragma unroll
            for (int mt = 0; mt < 4; ++mt)
#pragma unroll
                for (int nt = 0; nt < 4; ++nt) mma8(acc[mt][nt], a[mt], b[nt]);
        }
    }

#pragma unroll
    for (int mt = 0; mt < 4; ++mt) {
#pragma unroll
        for (int nt = 0; nt < 4; ++nt) {
            int row = row0 + wm + mt * 16 + g;
            int col = n0 + wn + nt * 8 + 2 * tig;
            float b0 = __ldg(bias + col), b1 = __ldg(bias + col + 1);
            float v0 = fmaxf(acc[mt][nt][0] + b0, 0.f);
            float v1 = fmaxf(acc[mt][nt][1] + b1, 0.f);
            float v2 = fmaxf(acc[mt][nt][2] + b0, 0.f);
            float v3 = fmaxf(acc[mt][nt][3] + b1, 0.f);
            *(__nv_bfloat162*)&g_Hb[(size_t)row * 256 + col] =
                __floats2bfloat162_rn(v0, v1);
            *(__nv_bfloat162*)&g_Hb[(size_t)(row + 8) * 256 + col] =
                __floats2bfloat162_rn(v2, v3);
        }
    }
}

// ============ K2: bf16 GEMM tok = H @ W2^T + b2 (fp32 out) ============
__global__ __launch_bounds__(256) void k2_gemm(const float* __restrict__ bias) {
    __shared__ __nv_bfloat16 As[2][128][24];
    __shared__ __nv_bfloat16 Bs[2][128][24];
    const int tid = threadIdx.x;
    const int lane = tid & 31, w = tid >> 5;
    const int row0 = blockIdx.x * 128, n0 = blockIdx.y * 128;
    const int wm = (w & 1) * 64, wn = (w >> 1) * 32;
    const int g = lane >> 2, tig = lane & 3;

    float acc[4][4][4] = {};

    auto loadTile = [&](int s, int kt) {
        const int kb = kt * 16;
        {
            int r = tid >> 1, off = (tid & 1) * 8;
            cp16((unsigned)__cvta_generic_to_shared(&As[s][r][off]),
                 g_Hb + (size_t)(row0 + r) * 256 + kb + off);
        }
        {
            int n = tid >> 1, off = (tid & 1) * 8;
            cp16((unsigned)__cvta_generic_to_shared(&Bs[s][n][off]),
                 g_W2b + (size_t)(n0 + n) * 256 + kb + off);
        }
    };

    loadTile(0, 0);
    CP_COMMIT;
    for (int kt = 0; kt < 16; ++kt) {
        CP_WAIT0;
        __syncthreads();
        if (kt + 1 < 16) {
            loadTile((kt + 1) & 1, kt + 1);
            CP_COMMIT;
        }
        const int s = kt & 1;
        unsigned a[4][4], b[4][2];
#pragma unroll
        for (int mt = 0; mt < 4; ++mt) {
            int r = wm + mt * 16 + g;
            a[mt][0] = *(const unsigned*)&As[s][r][tig * 2];
            a[mt][1] = *(const unsigned*)&As[s][r + 8][tig * 2];
            a[mt][2] = *(const unsigned*)&As[s][r][tig * 2 + 8];
            a[mt][3] = *(const unsigned*)&As[s][r + 8][tig * 2 + 8];
        }
#pragma unroll
        for (int nt = 0; nt < 4; ++nt) {
            int n = wn + nt * 8 + g;
            b[nt][0] = *(const unsigned*)&Bs[s][n][tig * 2];
            b[nt][1] = *(const unsigned*)&Bs[s][n][tig * 2 + 8];
        }
#pragma unroll
        for (int mt = 0; mt < 4; ++mt)
#pragma unroll
            for (int nt = 0; nt < 4; ++nt) mma16(acc[mt][nt], a[mt], b[nt]);
    }

#pragma unroll
    for (int mt = 0; mt < 4; ++mt) {
#pragma unroll
        for (int nt = 0; nt < 4; ++nt) {
            int row = row0 + wm + mt * 16 + g;
            int col = n0 + wn + nt * 8 + 2 * tig;
            float b0 = __ldg(bias + col), b1 = __ldg(bias + col + 1);
            float2 p0 = {acc[mt][nt][0] + b0, acc[mt][nt][1] + b1};
            float2 p1 = {acc[mt][nt][2] + b0, acc[mt][nt][3] + b1};
            *(float2*)&g_tok[(size_t)row * 512 + col] = p0;
            *(float2*)&g_tok[(size_t)(row + 8) * 512 + col] = p1;
        }
    }
}

// ============ K3a: block-coop s1, scores, softmax, entropy, wtok(bf16) ============
#define K3A_SMEM_FLOATS 14016
#define K3A_SMEM_BYTES (K3A_SMEM_FLOATS * 4)

__global__ __launch_bounds__(256) void k3a_attn(const float* __restrict__ obs,
                                                float* __restrict__ out_ent) {
    extern __shared__ float sm[];
    float* toks  = sm;              // 16*544 = 8704
    float* s1S   = toks + 8704;     // 16*272 = 4352
    float* rootS = s1S + 4352;      // 192
    float* attnS = rootS + 192;     // 512

    const int tid = threadIdx.x;
    const int lane = tid & 31, w = tid >> 5;
    const int row0 = blockIdx.x * 16;

    {
        const float* src = g_tok + (size_t)row0 * 512;
#pragma unroll
        for (int l = 0; l < 8; ++l) {
            int idx = (tid + l * 256) * 4;
            int r = idx >> 9, c = idx & 511;
            cp16((unsigned)__cvta_generic_to_shared(
                     &toks[r * 544 + (c >> 6) * 68 + (c & 63)]),
                 src + (size_t)r * 512 + c);
        }
    }
    CP_COMMIT;
    for (int idx = tid; idx < 176; idx += 256) {
        int r = idx / 11, j = idx % 11;
        int col = (j < 5) ? j : (17 + j);
        rootS[r * 12 + j] = obs[(size_t)(row0 + r) * 376 + col];
    }
    float a1[11];
#pragma unroll
    for (int t = 0; t < 11; ++t) a1[t] = g_A1T[t * 256 + tid];
    const float c1v = g_c1[tid];
    CP_WAIT0;
    __syncthreads();

    {
        const int dst = (tid >> 6) * 68 + (tid & 63);
#pragma unroll
        for (int r = 0; r < 16; ++r) {
            float acc = c1v;
#pragma unroll
            for (int t = 0; t < 11; ++t) acc = fmaf(rootS[r * 12 + t], a1[t], acc);
            s1S[r * 272 + dst] = acc;
        }
    }
    __syncthreads();

    const int h = lane >> 3, t = lane & 7;
    const int hh = lane >> 3;
    const int jb = (lane * 8) & 63;
#pragma unroll
    for (int rr = 0; rr < 2; ++rr) {
        const int r = w * 2 + rr;
        const size_t row = (size_t)row0 + r;
        float4 sv = {0.f, 0.f, 0.f, 0.f};
        const float* s1p = &s1S[r * 272 + h * 68];
        const float* tp  = &toks[r * 544 + t * 68];
#pragma unroll
        for (int j4 = 0; j4 < 16; ++j4) {
            float4 a4 = *(const float4*)(s1p + 4 * j4);
            float4 b4 = *(const float4*)(tp + 4 * j4);
            sv.x = fmaf(a4.x, b4.x, sv.x);
            sv.y = fmaf(a4.y, b4.y, sv.y);
            sv.z = fmaf(a4.z, b4.z, sv.z);
            sv.w = fmaf(a4.w, b4.w, sv.w);
        }
        float s = (sv.x + sv.y + sv.z + sv.w) * 0.25f;
        float m = s;
        m = fmaxf(m, __shfl_xor_sync(0xffffffffu, m, 1, 8));
        m = fmaxf(m, __shfl_xor_sync(0xffffffffu, m, 2, 8));
        m = fmaxf(m, __shfl_xor_sync(0xffffffffu, m, 4, 8));
        float ex = expf(s - m);
        float den = ex;
        den += __shfl_xor_sync(0xffffffffu, den, 1, 8);
        den += __shfl_xor_sync(0xffffffffu, den, 2, 8);
        den += __shfl_xor_sync(0xffffffffu, den, 4, 8);
        float a = ex / den;
        attnS[r * 32 + lane] = a;
        float ah = a;
        ah += __shfl_xor_sync(0xffffffffu, ah, 8);
        ah += __shfl_xor_sync(0xffffffffu, ah, 16);
        float aw = fmaxf(ah * 0.25f, 1e-8f);
        float term = -aw * logf(aw);
        term += __shfl_xor_sync(0xffffffffu, term, 1, 8);
        term += __shfl_xor_sync(0xffffffffu, term, 2, 8);
        term += __shfl_xor_sync(0xffffffffu, term, 4, 8);
        if (lane == 0) out_ent[row] = term;
        __syncwarp();
        float av[8];
#pragma unroll
        for (int tt = 0; tt < 8; ++tt) av[tt] = attnS[r * 32 + hh * 8 + tt];
        float4 acc0 = {0.f, 0.f, 0.f, 0.f}, acc1 = {0.f, 0.f, 0.f, 0.f};
        const float* tb = &toks[r * 544 + jb];
#pragma unroll
        for (int tt = 0; tt < 8; ++tt) {
            float4 t0 = *(const float4*)(tb + tt * 68);
            float4 t1 = *(const float4*)(tb + tt * 68 + 4);
            float av_ = av[tt];
            acc0.x = fmaf(av_, t0.x, acc0.x);
            acc0.y = fmaf(av_, t0.y, acc0.y);
            acc0.z = fmaf(av_, t0.z, acc0.z);
            acc0.w = fmaf(av_, t0.w, acc0.w);
            acc1.x = fmaf(av_, t1.x, acc1.x);
            acc1.y = fmaf(av_, t1.y, acc1.y);
            acc1.z = fmaf(av_, t1.z, acc1.z);
            acc1.w = fmaf(av_, t1.w, acc1.w);
        }
        __nv_bfloat162 pk[4];
        pk[0] = __floats2bfloat162_rn(acc0.x, acc0.y);
        pk[1] = __floats2bfloat162_rn(acc0.z, acc0.w);
        pk[2] = __floats2bfloat162_rn(acc1.x, acc1.y);
        pk[3] = __floats2bfloat162_rn(acc1.z, acc1.w);
        *(uint4*)&g_wtokb[row * 256 + lane * 8] = *(uint4*)pk;
    }
}

// ============ K4: bf16 GEMM y = wtok@G^T + cb, + remb + LN + head ============
#define K4_SMEM_FLOATS 13184
#define K4_SMEM_BYTES (K4_SMEM_FLOATS * 4)

__global__ __launch_bounds__(256) void k4_out_ln_head(
    const float* __restrict__ obs,
    const float* __restrict__ Wr, const float* __restrict__ br,
    const float* __restrict__ gamma, const float* __restrict__ beta,
    const float* __restrict__ Wh1, const float* __restrict__ bh1,
    const float* __restrict__ Wh2, const float* __restrict__ bh2,
    float* __restrict__ out_ctx) {
    extern __shared__ float sm[];
    __nv_bfloat16* Asb = (__nv_bfloat16*)sm;        // 2*128*24 = 6144 el (12288B)
    __nv_bfloat16* Bsb = Asb + 2 * 128 * 24;        // 2*64*24 = 3072 el (6144B)
    float* ys = sm;                 // epi: 128*68 = 8704 (reuses GEMM smem)
    float* Wh1S  = sm + 8704;       // 32*68 = 2176
    float* WrS   = sm + 10880;      // 768
    float* rootS = sm + 11648;      // 1536

    const int tid = threadIdx.x;
    const int lane = tid & 31, w = tid >> 5;
    const int row0 = blockIdx.x * 128;
    const int wm = (w & 3) * 32, wn = (w >> 2) * 32;
    const int g = lane >> 2, tig = lane & 3;

    float acc[2][4][4] = {};

    auto loadTile = [&](int s, int kt) {
        const int kb = kt * 16;
        {
            int r = tid >> 1, off = (tid & 1) * 8;
            cp16((unsigned)__cvta_generic_to_shared(&Asb[(s * 128 + r) * 24 + off]),
                 g_wtokb + (size_t)(row0 + r) * 256 + kb + off);
        }
        if (tid < 128) {
            int n = tid >> 1, off = (tid & 1) * 8;
            cp16((unsigned)__cvta_generic_to_shared(&Bsb[(s * 64 + n) * 24 + off]),
                 g_Gb + (size_t)n * 256 + kb + off);
        }
    };

    loadTile(0, 0);
    CP_COMMIT;
    for (int kt = 0; kt < 16; ++kt) {
        CP_WAIT0;
        __syncthreads();
        if (kt + 1 < 16) {
            loadTile((kt + 1) & 1, kt + 1);
            CP_COMMIT;
        }
        const int s = kt & 1;
        unsigned a[2][4], b[4][2];
#pragma unroll
        for (int mt = 0; mt < 2; ++mt) {
            int r = wm + mt * 16 + g;
            a[mt][0] = *(const unsigned*)&Asb[(s * 128 + r) * 24 + tig * 2];
            a[mt][1] = *(const unsigned*)&Asb[(s * 128 + r + 8) * 24 + tig * 2];
            a[mt][2] = *(const unsigned*)&Asb[(s * 128 + r) * 24 + tig * 2 + 8];
            a[mt][3] = *(const unsigned*)&Asb[(s * 128 + r + 8) * 24 + tig * 2 + 8];
        }
#pragma unroll
        for (int nt = 0; nt < 4; ++nt) {
            int n = wn + nt * 8 + g;
            b[nt][0] = *(const unsigned*)&Bsb[(s * 64 + n) * 24 + tig * 2];
            b[nt][1] = *(const unsigned*)&Bsb[(s * 64 + n) * 24 + tig * 2 + 8];
        }
#pragma unroll
        for (int mt = 0; mt < 2; ++mt)
#pragma unroll
            for (int nt = 0; nt < 4; ++nt) mma16(acc[mt][nt], a[mt], b[nt]);
    }
    __syncthreads();   // done with GEMM smem; reuse as ys

#pragma unroll
    for (int mt = 0; mt < 2; ++mt) {
#pragma unroll
        for (int nt = 0; nt < 4; ++nt) {
            int r = wm + mt * 16 + g;
            int col = wn + nt * 8 + 2 * tig;
            float c0 = g_cb[col], c1 = g_cb[col + 1];
            ys[r * 68 + col]           = acc[mt][nt][0] + c0;
            ys[r * 68 + col + 1]       = acc[mt][nt][1] + c1;
            ys[(r + 8) * 68 + col]     = acc[mt][nt][2] + c0;
            ys[(r + 8) * 68 + col + 1] = acc[mt][nt][3] + c1;
        }
    }
    for (int idx = tid; idx < 2048; idx += 256)
        Wh1S[(idx >> 6) * 68 + (idx & 63)] = Wh1[idx];
    for (int idx = tid; idx < 704; idx += 256)
        WrS[(idx / 11) * 12 + (idx % 11)] = Wr[idx];
    for (int idx = tid; idx < 1408; idx += 256) {
        int r = idx / 11, j = idx % 11;
        int col = (j < 5) ? j : (17 + j);
        rootS[r * 12 + j] = obs[(size_t)(row0 + r) * 376 + col];
    }
    __syncthreads();

    const float gm0 = gamma[lane], gm1 = gamma[lane + 32];
    const float bt0 = beta[lane],  bt1 = beta[lane + 32];
    const float br0 = br[lane],    br1 = br[lane + 32];
    const float bh1v = bh1[lane], wh2v = Wh2[lane], bh2v = bh2[0];

#pragma unroll 2
    for (int rr = 0; rr < 16; ++rr) {
        const int r = w * 16 + rr;
        const size_t row = (size_t)row0 + r;
        float e0 = br0, e1 = br1;
#pragma unroll
        for (int j = 0; j < 11; ++j) {
            float rv = rootS[r * 12 + j];
            e0 = fmaf(rv, WrS[lane * 12 + j], e0);
            e1 = fmaf(rv, WrS[(lane + 32) * 12 + j], e1);
        }
        float x0 = ys[r * 68 + lane] + e0;
        float x1 = ys[r * 68 + lane + 32] + e1;
        float ssum = x0 + x1;
#pragma unroll
        for (int o = 16; o > 0; o >>= 1) ssum += __shfl_xor_sync(0xffffffffu, ssum, o);
        float mu = ssum * (1.f / 64.f);
        float d0 = x0 - mu, d1 = x1 - mu;
        float vs = d0 * d0 + d1 * d1;
#pragma unroll
        for (int o = 16; o > 0; o >>= 1) vs += __shfl_xor_sync(0xffffffffu, vs, o);
        float inv = rsqrtf(vs * (1.f / 64.f) + 1e-5f);
        float c0 = fmaf(gm0, d0 * inv, bt0);
        float c1 = fmaf(gm1, d1 * inv, bt1);
        out_ctx[row * 64 + lane] = c0;
        out_ctx[row * 64 + lane + 32] = c1;
        ys[r * 68 + lane] = c0;
        ys[r * 68 + lane + 32] = c1;
        __syncwarp();
        float4 hv = {0.f, 0.f, 0.f, 0.f};
#pragma unroll
        for (int d4 = 0; d4 < 16; ++d4) {
            float4 yv = *(const float4*)&ys[r * 68 + 4 * d4];
            float4 wv = *(const float4*)&Wh1S[lane * 68 + 4 * d4];
            hv.x = fmaf(yv.x, wv.x, hv.x);
            hv.y = fmaf(yv.y, wv.y, hv.y);
            hv.z = fmaf(yv.z, wv.z, hv.z);
            hv.w = fmaf(yv.w, wv.w, hv.w);
        }
        float v = fmaxf(hv.x + hv.y + hv.z + hv.w + bh1v, 0.f) * wh2v;
#pragma unroll
        for (int o = 16; o > 0; o >>= 1) v += __shfl_xor_sync(0xffffffffu, v, o);
        if (lane == 0) g_raw[row] = v + bh2v;
        __syncwarp();
    }
}

// ================= batch reductions =================
__global__ void k_reduce_raw() {
    __shared__ float s[256];
    int tid = threadIdx.x;
    int i = blockIdx.x * 512 + tid;
    s[tid] = g_raw[i] + g_raw[i + 256];
    __syncthreads();
    for (int o = 128; o > 0; o >>= 1) {
        if (tid < o) s[tid] += s[tid + o];
        __syncthreads();
    }
    if (tid == 0) g_part[blockIdx.x] = s[0];
}
__global__ void k_finish_raw() {
    __shared__ float s[256];
    int tid = threadIdx.x;
    s[tid] = g_part[tid];
    __syncthreads();
    for (int o = 128; o > 0; o >>= 1) {
        if (tid < o) s[tid] += s[tid + o];
        __syncthreads();
    }
    if (tid == 0) g_scalars[0] = s[0] * (1.f / (float)BATCH);
}
__global__ void k_reduce_lw() {
    __shared__ float s[256];
    int tid = threadIdx.x;
    float mean = g_scalars[0];
    int i = blockIdx.x * 512 + tid;
    s[tid] = expf(0.5f * tanhf(g_raw[i] - mean)) +
             expf(0.5f * tanhf(g_raw[i + 256] - mean));
    __syncthreads();
    for (int o = 128; o > 0; o >>= 1) {
        if (tid < o) s[tid] += s[tid + o];
        __syncthreads();
    }
    if (tid == 0) g_part[blockIdx.x] = s[0];
}
__global__ void k_finish_lw() {
    __shared__ float s[256];
    int tid = threadIdx.x;
    s[tid] = g_part[tid];
    __syncthreads();
    for (int o = 128; o > 0; o >>= 1) {
        if (tid < o) s[tid] += s[tid + o];
        __syncthreads();
    }
    if (tid == 0) g_scalars[1] = fmaxf(s[0] * (1.f / (float)BATCH), 1e-6f);
}
__global__ void k_write_lw(float* __restrict__ out_lw) {
    int i = blockIdx.x * 256 + threadIdx.x;
    float lw = expf(0.5f * tanhf(g_raw[i] - g_scalars[0]));
    out_lw[i] = lw / g_scalars[1];
}

// =====================================================================
extern "C" void kernel_launch(void* const* d_in, const int* in_sizes, int n_in,
                              void* d_out, int out_size) {
    const float* obs   = (const float*)d_in[0];
    const float* W1    = (const float*)d_in[1];
    const float* b1    = (const float*)d_in[2];
    const float* W2    = (const float*)d_in[3];
    const float* b2    = (const float*)d_in[4];
    const float* Wr    = (const float*)d_in[5];
    const float* br    = (const float*)d_in[6];
    const float* Win   = (const float*)d_in[7];
    const float* bin_  = (const float*)d_in[8];
    const float* Wout  = (const float*)d_in[9];
    const float* bout  = (const float*)d_in[10];
    const float* gamma = (const float*)d_in[11];
    const float* beta  = (const float*)d_in[12];
    const float* Wh1   = (const float*)d_in[13];
    const float* bh1   = (const float*)d_in[14];
    const float* Wh2   = (const float*)d_in[15];
    const float* bh2   = (const float*)d_in[16];

    float* out     = (float*)d_out;
    float* out_ctx = out;
    float* out_lw  = out + (size_t)BATCH * 64;
    float* out_ent = out_lw + BATCH;

    cudaFuncSetAttribute(k3a_attn, cudaFuncAttributeMaxDynamicSharedMemorySize,
                         K3A_SMEM_BYTES);
    cudaFuncSetAttribute(k4_out_ln_head, cudaFuncAttributeMaxDynamicSharedMemorySize,
                         K4_SMEM_BYTES);

    k0_fold<<<8, 256>>>(Wr, br, Win, bin_, Wout, bout, W2);
    k1_gemm<<<dim3(BATCH / 128, 2), 256>>>(obs, W1, b1);
    k2_gemm<<<dim3(BATCH / 128, 4), 256>>>(b2);
    k3a_attn<<<BATCH / 16, 256, K3A_SMEM_BYTES>>>(obs, out_ent);
    k4_out_ln_head<<<BATCH / 128, 256, K4_SMEM_BYTES>>>(
        obs, Wr, br, gamma, beta, Wh1, bh1, Wh2, bh2, out_ctx);
    k_reduce_raw<<<256, 256>>>();
    k_finish_raw<<<1, 256>>>();
    k_reduce_lw<<<256, 256>>>();
    k_finish_lw<<<1, 256>>>();
    k_write_lw<<<BATCH / 256, 256>>>(out_lw);
}

// round 10
// speedup vs baseline: 6.9828x; 1.0720x over previous
#include <cuda_runtime.h>
#include <cuda_bf16.h>
#include <math.h>

#define BATCH 131072

__device__ __nv_bfloat16 g_Hb[(size_t)BATCH * 256];
__device__ __nv_bfloat16 g_tokb[(size_t)BATCH * 512];
__device__ __nv_bfloat16 g_wtokb[(size_t)BATCH * 256];
__device__ float g_raw[BATCH];
__device__ float g_part[256];
__device__ float g_scalars[2];
// folded weights
__device__ float g_A1T[12 * 256];           // [t][hj]
__device__ float g_c1[256];
__device__ __nv_bfloat16 g_Gb[64 * 256];    // [e][hj] bf16
__device__ float g_cb[64];
__device__ __nv_bfloat16 g_W2b[512 * 256];

// ---------------- helpers ----------------
__device__ __forceinline__ unsigned cvt_tf32(float x) {
    unsigned u;
    asm("cvt.rna.tf32.f32 %0, %1;" : "=r"(u) : "f"(x));
    return u;
}
__device__ __forceinline__ void cp4(unsigned dst, const void* src, unsigned sz) {
    asm volatile("cp.async.ca.shared.global [%0], [%1], 4, %2;" ::
                 "r"(dst), "l"(src), "r"(sz));
}
__device__ __forceinline__ void cp16(unsigned dst, const void* src) {
    asm volatile("cp.async.cg.shared.global [%0], [%1], 16;" ::
                 "r"(dst), "l"(src));
}
__device__ __forceinline__ void cp16z(unsigned dst, const void* src, unsigned sz) {
    asm volatile("cp.async.cg.shared.global [%0], [%1], 16, %2;" ::
                 "r"(dst), "l"(src), "r"(sz));
}
#define CP_COMMIT asm volatile("cp.async.commit_group;")
#define CP_WAIT0  asm volatile("cp.async.wait_group 0;")

__device__ __forceinline__ void mma8(float* d, const unsigned* a, const unsigned* b) {
    asm volatile(
        "mma.sync.aligned.m16n8k8.row.col.f32.tf32.tf32.f32 "
        "{%0,%1,%2,%3}, {%4,%5,%6,%7}, {%8,%9}, {%0,%1,%2,%3};"
        : "+f"(d[0]), "+f"(d[1]), "+f"(d[2]), "+f"(d[3])
        : "r"(a[0]), "r"(a[1]), "r"(a[2]), "r"(a[3]), "r"(b[0]), "r"(b[1]));
}
__device__ __forceinline__ void mma16(float* d, const unsigned* a, const unsigned* b) {
    asm volatile(
        "mma.sync.aligned.m16n8k16.row.col.f32.bf16.bf16.f32 "
        "{%0,%1,%2,%3}, {%4,%5,%6,%7}, {%8,%9}, {%0,%1,%2,%3};"
        : "+f"(d[0]), "+f"(d[1]), "+f"(d[2]), "+f"(d[3])
        : "r"(a[0]), "r"(a[1]), "r"(a[2]), "r"(a[3]), "r"(b[0]), "r"(b[1]));
}
__device__ __forceinline__ float2 bf2f(unsigned u) {
    __nv_bfloat162 b = *(__nv_bfloat162*)&u;
    return __bfloat1622float2(b);
}

// ============ K0: fold precompute + bf16 weight conversion ============
__global__ __launch_bounds__(256) void k0_fold(
    const float* __restrict__ Wr, const float* __restrict__ br,
    const float* __restrict__ Win, const float* __restrict__ bin_,
    const float* __restrict__ Wout, const float* __restrict__ bout,
    const float* __restrict__ W2) {
    __shared__ float QW[64 * 12];
    __shared__ float qsS[64];
    const int tid = threadIdx.x, bx = blockIdx.x;

    if (bx == 0) {
        for (int idx = tid; idx < 704; idx += 256) {
            int e = idx / 11, t = idx % 11;
            float acc = 0.f;
            for (int d = 0; d < 64; ++d) acc = fmaf(Win[e * 64 + d], Wr[d * 11 + t], acc);
            QW[e * 12 + t] = acc;
        }
        for (int idx = tid; idx < 64; idx += 256) {
            float acc = bin_[idx];
            for (int d = 0; d < 64; ++d) acc = fmaf(Win[idx * 64 + d], br[d], acc);
            qsS[idx] = acc;
        }
        __syncthreads();
        for (int idx = tid; idx < 2816; idx += 256) {
            int hj = idx / 11, t = idx % 11;
            int h = hj >> 6, j = hj & 63;
            float acc = 0.f;
            for (int e = 0; e < 16; ++e) {
                int x = h * 16 + e;
                acc = fmaf(Win[4096 + x * 64 + j], QW[x * 12 + t], acc);
            }
            g_A1T[t * 256 + hj] = acc;
        }
        for (int idx = tid; idx < 256; idx += 256) {
            int h = idx >> 6, j = idx & 63;
            float acc = 0.f;
            for (int e = 0; e < 16; ++e) {
                int x = h * 16 + e;
                acc = fmaf(Win[4096 + x * 64 + j], qsS[x], acc);
            }
            g_c1[idx] = acc;
        }
        for (int idx = tid; idx < 64; idx += 256) {
            float acc = bout[idx];
            for (int d = 0; d < 64; ++d) acc = fmaf(Wout[idx * 64 + d], bin_[128 + d], acc);
            g_cb[idx] = acc;
        }
    }
    for (int idx = tid; idx < 2048; idx += 256) {
        int e = bx * 8 + (idx >> 8);
        int hj = idx & 255, h = hj >> 6, j = hj & 63;
        float acc = 0.f;
        for (int d = 0; d < 16; ++d)
            acc = fmaf(Wout[e * 64 + h * 16 + d], Win[8192 + (h * 16 + d) * 64 + j], acc);
        g_Gb[e * 256 + hj] = __float2bfloat16(acc);
    }
    for (int idx = bx * 16384 + tid; idx < (bx + 1) * 16384; idx += 256)
        g_W2b[idx] = __float2bfloat16(W2[idx]);
}

// ============ K1: tf32 gather GEMM, bf16 output H ============
__global__ __launch_bounds__(256) void k1_gemm(const float* __restrict__ A,
                                               const float* __restrict__ W,
                                               const float* __restrict__ bias) {
    __shared__ float As[2][128][20];
    __shared__ float Bs[2][128][20];
    const int tid = threadIdx.x;
    const int lane = tid & 31, w = tid >> 5;
    const int row0 = blockIdx.x * 128, n0 = blockIdx.y * 128;
    const int wm = (w & 1) * 64, wn = (w >> 1) * 32;
    const int g = lane >> 2, tig = lane & 3;
    const int LDA = 376, KROW = 308;

    float acc[4][4][4] = {};

    auto loadTile = [&](int s, int kt) {
        const int kb = kt * 16;
#pragma unroll
        for (int l = 0; l < 8; ++l) {
            int idx = tid + l * 256;
            int r = idx >> 4, kk = idx & 15;
            int k = kb + kk;
            int col = (k < 224) ? (45 + k) : (68 + k);
            const float* src = A + (size_t)(row0 + r) * LDA + ((k < KROW) ? col : 0);
            cp4((unsigned)__cvta_generic_to_shared(&As[s][r][kk]), src,
                (k < KROW) ? 4u : 0u);
        }
#pragma unroll
        for (int l = 0; l < 2; ++l) {
            int idx = tid + l * 256;
            int n = idx >> 2, c = (idx & 3) * 4;
            int k = kb + c;
            cp16z((unsigned)__cvta_generic_to_shared(&Bs[s][n][c]),
                  W + (size_t)(n0 + n) * KROW + ((k < KROW) ? k : 0),
                  (k + 4 <= KROW) ? 16u : 0u);
        }
    };

    loadTile(0, 0);
    CP_COMMIT;

    for (int kt = 0; kt < 20; ++kt) {
        CP_WAIT0;
        __syncthreads();
        if (kt + 1 < 20) {
            loadTile((kt + 1) & 1, kt + 1);
            CP_COMMIT;
        }
        const int s = kt & 1;
#pragma unroll
        for (int km = 0; km < 2; ++km) {
            unsigned a[4][4], b[4][2];
            const int k0 = km * 8 + tig;
#pragma unroll
            for (int mt = 0; mt < 4; ++mt) {
                int r = wm + mt * 16 + g;
                a[mt][0] = cvt_tf32(As[s][r][k0]);
                a[mt][1] = cvt_tf32(As[s][r + 8][k0]);
                a[mt][2] = cvt_tf32(As[s][r][k0 + 4]);
                a[mt][3] = cvt_tf32(As[s][r + 8][k0 + 4]);
            }
#pragma unroll
            for (int nt = 0; nt < 4; ++nt) {
                int n = wn + nt * 8 + g;
                b[nt][0] = cvt_tf32(Bs[s][n][k0]);
                b[nt][1] = cvt_tf32(Bs[s][n][k0 + 4]);
            }
#pragma unroll
            for (int mt = 0; mt < 4; ++mt)
#pragma unroll
                for (int nt = 0; nt < 4; ++nt) mma8(acc[mt][nt], a[mt], b[nt]);
        }
    }

#pragma unroll
    for (int mt = 0; mt < 4; ++mt) {
#pragma unroll
        for (int nt = 0; nt < 4; ++nt) {
            int row = row0 + wm + mt * 16 + g;
            int col = n0 + wn + nt * 8 + 2 * tig;
            float b0 = __ldg(bias + col), b1 = __ldg(bias + col + 1);
            float v0 = fmaxf(acc[mt][nt][0] + b0, 0.f);
            float v1 = fmaxf(acc[mt][nt][1] + b1, 0.f);
            float v2 = fmaxf(acc[mt][nt][2] + b0, 0.f);
            float v3 = fmaxf(acc[mt][nt][3] + b1, 0.f);
            *(__nv_bfloat162*)&g_Hb[(size_t)row * 256 + col] =
                __floats2bfloat162_rn(v0, v1);
            *(__nv_bfloat162*)&g_Hb[(size_t)(row + 8) * 256 + col] =
                __floats2bfloat162_rn(v2, v3);
        }
    }
}

// ============ K2: bf16 GEMM tok = H @ W2^T + b2 (bf16 out) ============
__global__ __launch_bounds__(256) void k2_gemm(const float* __restrict__ bias) {
    __shared__ __nv_bfloat16 As[2][128][24];
    __shared__ __nv_bfloat16 Bs[2][128][24];
    const int tid = threadIdx.x;
    const int lane = tid & 31, w = tid >> 5;
    const int row0 = blockIdx.x * 128, n0 = blockIdx.y * 128;
    const int wm = (w & 1) * 64, wn = (w >> 1) * 32;
    const int g = lane >> 2, tig = lane & 3;

    float acc[4][4][4] = {};

    auto loadTile = [&](int s, int kt) {
        const int kb = kt * 16;
        {
            int r = tid >> 1, off = (tid & 1) * 8;
            cp16((unsigned)__cvta_generic_to_shared(&As[s][r][off]),
                 g_Hb + (size_t)(row0 + r) * 256 + kb + off);
        }
        {
            int n = tid >> 1, off = (tid & 1) * 8;
            cp16((unsigned)__cvta_generic_to_shared(&Bs[s][n][off]),
                 g_W2b + (size_t)(n0 + n) * 256 + kb + off);
        }
    };

    loadTile(0, 0);
    CP_COMMIT;
    for (int kt = 0; kt < 16; ++kt) {
        CP_WAIT0;
        __syncthreads();
        if (kt + 1 < 16) {
            loadTile((kt + 1) & 1, kt + 1);
            CP_COMMIT;
        }
        const int s = kt & 1;
        unsigned a[4][4], b[4][2];
#pragma unroll
        for (int mt = 0; mt < 4; ++mt) {
            int r = wm + mt * 16 + g;
            a[mt][0] = *(const unsigned*)&As[s][r][tig * 2];
            a[mt][1] = *(const unsigned*)&As[s][r + 8][tig * 2];
            a[mt][2] = *(const unsigned*)&As[s][r][tig * 2 + 8];
            a[mt][3] = *(const unsigned*)&As[s][r + 8][tig * 2 + 8];
        }
#pragma unroll
        for (int nt = 0; nt < 4; ++nt) {
            int n = wn + nt * 8 + g;
            b[nt][0] = *(const unsigned*)&Bs[s][n][tig * 2];
            b[nt][1] = *(const unsigned*)&Bs[s][n][tig * 2 + 8];
        }
#pragma unroll
        for (int mt = 0; mt < 4; ++mt)
#pragma unroll
            for (int nt = 0; nt < 4; ++nt) mma16(acc[mt][nt], a[mt], b[nt]);
    }

#pragma unroll
    for (int mt = 0; mt < 4; ++mt) {
#pragma unroll
        for (int nt = 0; nt < 4; ++nt) {
            int row = row0 + wm + mt * 16 + g;
            int col = n0 + wn + nt * 8 + 2 * tig;
            float b0 = __ldg(bias + col), b1 = __ldg(bias + col + 1);
            *(__nv_bfloat162*)&g_tokb[(size_t)row * 512 + col] =
                __floats2bfloat162_rn(acc[mt][nt][0] + b0, acc[mt][nt][1] + b1);
            *(__nv_bfloat162*)&g_tokb[(size_t)(row + 8) * 512 + col] =
                __floats2bfloat162_rn(acc[mt][nt][2] + b0, acc[mt][nt][3] + b1);
        }
    }
}

// ============ K3a: bf16 toks, block-coop s1, scores, softmax, entropy, wtok ============
// smem: toksb 16*576 bf16 (4608 fl) | s1S 16*272 fl | rootS 192 | attnS 512
#define K3A_SMEM_FLOATS 9664
#define K3A_SMEM_BYTES (K3A_SMEM_FLOATS * 4)

__global__ __launch_bounds__(256) void k3a_attn(const float* __restrict__ obs,
                                                float* __restrict__ out_ent) {
    extern __shared__ float sm[];
    __nv_bfloat16* toksb = (__nv_bfloat16*)sm;   // 16 rows * 576 (token stride 72)
    float* s1S   = sm + 4608;       // 16*272
    float* rootS = s1S + 4352;      // 192
    float* attnS = rootS + 192;     // 512

    const int tid = threadIdx.x;
    const int lane = tid & 31, w = tid >> 5;
    const int row0 = blockIdx.x * 16;

    // stage toks bf16: 8192 elems, 8 per cp16
    {
        const __nv_bfloat16* src = g_tokb + (size_t)row0 * 512;
#pragma unroll
        for (int l = 0; l < 4; ++l) {
            int idx = (tid + l * 256) * 8;
            int r = idx >> 9, c = idx & 511;
            cp16((unsigned)__cvta_generic_to_shared(
                     &toksb[r * 576 + (c >> 6) * 72 + (c & 63)]),
                 src + (size_t)r * 512 + c);
        }
    }
    CP_COMMIT;
    for (int idx = tid; idx < 176; idx += 256) {
        int r = idx / 11, j = idx % 11;
        int col = (j < 5) ? j : (17 + j);
        rootS[r * 12 + j] = obs[(size_t)(row0 + r) * 376 + col];
    }
    float a1[11];
#pragma unroll
    for (int t = 0; t < 11; ++t) a1[t] = g_A1T[t * 256 + tid];
    const float c1v = g_c1[tid];
    CP_WAIT0;
    __syncthreads();

    // block-cooperative s1: tid owns hj=tid, all 16 rows
    {
        const int dst = (tid >> 6) * 68 + (tid & 63);
#pragma unroll
        for (int r = 0; r < 16; ++r) {
            float acc = c1v;
#pragma unroll
            for (int t = 0; t < 11; ++t) acc = fmaf(rootS[r * 12 + t], a1[t], acc);
            s1S[r * 272 + dst] = acc;
        }
    }
    __syncthreads();

    const int h = lane >> 3, t = lane & 7;
    const int hh = lane >> 3;
    const int jb = (lane & 7) * 8;      // j offset within token for wtok
#pragma unroll
    for (int rr = 0; rr < 2; ++rr) {
        const int r = w * 2 + rr;
        const size_t row = (size_t)row0 + r;
        // scores: 8 x uint4 (bf16) + 16 x float4 (s1)
        float4 sv = {0.f, 0.f, 0.f, 0.f};
        const float* s1p = &s1S[r * 272 + h * 68];
        const uint4* tpv = (const uint4*)(toksb + r * 576 + t * 72);
#pragma unroll
        for (int j8 = 0; j8 < 8; ++j8) {
            uint4 u = tpv[j8];
            float2 t0 = bf2f(u.x), t1 = bf2f(u.y), t2 = bf2f(u.z), t3 = bf2f(u.w);
            float4 a0 = *(const float4*)(s1p + 8 * j8);
            float4 a1_ = *(const float4*)(s1p + 8 * j8 + 4);
            sv.x = fmaf(a0.x, t0.x, sv.x);
            sv.y = fmaf(a0.y, t0.y, sv.y);
            sv.z = fmaf(a0.z, t1.x, sv.z);
            sv.w = fmaf(a0.w, t1.y, sv.w);
            sv.x = fmaf(a1_.x, t2.x, sv.x);
            sv.y = fmaf(a1_.y, t2.y, sv.y);
            sv.z = fmaf(a1_.z, t3.x, sv.z);
            sv.w = fmaf(a1_.w, t3.y, sv.w);
        }
        float s = (sv.x + sv.y + sv.z + sv.w) * 0.25f;
        float m = s;
        m = fmaxf(m, __shfl_xor_sync(0xffffffffu, m, 1, 8));
        m = fmaxf(m, __shfl_xor_sync(0xffffffffu, m, 2, 8));
        m = fmaxf(m, __shfl_xor_sync(0xffffffffu, m, 4, 8));
        float ex = expf(s - m);
        float den = ex;
        den += __shfl_xor_sync(0xffffffffu, den, 1, 8);
        den += __shfl_xor_sync(0xffffffffu, den, 2, 8);
        den += __shfl_xor_sync(0xffffffffu, den, 4, 8);
        float a = ex / den;
        attnS[r * 32 + lane] = a;
        float ah = a;
        ah += __shfl_xor_sync(0xffffffffu, ah, 8);
        ah += __shfl_xor_sync(0xffffffffu, ah, 16);
        float aw = fmaxf(ah * 0.25f, 1e-8f);
        float term = -aw * logf(aw);
        term += __shfl_xor_sync(0xffffffffu, term, 1, 8);
        term += __shfl_xor_sync(0xffffffffu, term, 2, 8);
        term += __shfl_xor_sync(0xffffffffu, term, 4, 8);
        if (lane == 0) out_ent[row] = term;
        __syncwarp();
        // wtok: lane owns 8 consecutive hj (head hh, j in [jb, jb+8))
        float av[8];
#pragma unroll
        for (int tt = 0; tt < 8; ++tt) av[tt] = attnS[r * 32 + hh * 8 + tt];
        float4 acc0 = {0.f, 0.f, 0.f, 0.f}, acc1 = {0.f, 0.f, 0.f, 0.f};
        const __nv_bfloat16* tb = toksb + r * 576 + jb;
#pragma unroll
        for (int tt = 0; tt < 8; ++tt) {
            uint4 u = *(const uint4*)(tb + tt * 72);
            float2 t0 = bf2f(u.x), t1 = bf2f(u.y), t2 = bf2f(u.z), t3 = bf2f(u.w);
            float av_ = av[tt];
            acc0.x = fmaf(av_, t0.x, acc0.x);
            acc0.y = fmaf(av_, t0.y, acc0.y);
            acc0.z = fmaf(av_, t1.x, acc0.z);
            acc0.w = fmaf(av_, t1.y, acc0.w);
            acc1.x = fmaf(av_, t2.x, acc1.x);
            acc1.y = fmaf(av_, t2.y, acc1.y);
            acc1.z = fmaf(av_, t3.x, acc1.z);
            acc1.w = fmaf(av_, t3.y, acc1.w);
        }
        __nv_bfloat162 pk[4];
        pk[0] = __floats2bfloat162_rn(acc0.x, acc0.y);
        pk[1] = __floats2bfloat162_rn(acc0.z, acc0.w);
        pk[2] = __floats2bfloat162_rn(acc1.x, acc1.y);
        pk[3] = __floats2bfloat162_rn(acc1.z, acc1.w);
        *(uint4*)&g_wtokb[row * 256 + lane * 8] = *(uint4*)pk;
    }
}

// ============ K4: bf16 GEMM y = wtok@G^T + cb, + remb + LN + head ============
#define K4_SMEM_FLOATS 13184
#define K4_SMEM_BYTES (K4_SMEM_FLOATS * 4)

__global__ __launch_bounds__(256) void k4_out_ln_head(
    const float* __restrict__ obs,
    const float* __restrict__ Wr, const float* __restrict__ br,
    const float* __restrict__ gamma, const float* __restrict__ beta,
    const float* __restrict__ Wh1, const float* __restrict__ bh1,
    const float* __restrict__ Wh2, const float* __restrict__ bh2,
    float* __restrict__ out_ctx) {
    extern __shared__ float sm[];
    __nv_bfloat16* Asb = (__nv_bfloat16*)sm;        // 2*128*24
    __nv_bfloat16* Bsb = Asb + 2 * 128 * 24;        // 2*64*24
    float* ys = sm;                 // epi: 128*68
    float* Wh1S  = sm + 8704;
    float* WrS   = sm + 10880;
    float* rootS = sm + 11648;

    const int tid = threadIdx.x;
    const int lane = tid & 31, w = tid >> 5;
    const int row0 = blockIdx.x * 128;
    const int wm = (w & 3) * 32, wn = (w >> 2) * 32;
    const int g = lane >> 2, tig = lane & 3;

    float acc[2][4][4] = {};

    auto loadTile = [&](int s, int kt) {
        const int kb = kt * 16;
        {
            int r = tid >> 1, off = (tid & 1) * 8;
            cp16((unsigned)__cvta_generic_to_shared(&Asb[(s * 128 + r) * 24 + off]),
                 g_wtokb + (size_t)(row0 + r) * 256 + kb + off);
        }
        if (tid < 128) {
            int n = tid >> 1, off = (tid & 1) * 8;
            cp16((unsigned)__cvta_generic_to_shared(&Bsb[(s * 64 + n) * 24 + off]),
                 g_Gb + (size_t)n * 256 + kb + off);
        }
    };

    loadTile(0, 0);
    CP_COMMIT;
    for (int kt = 0; kt < 16; ++kt) {
        CP_WAIT0;
        __syncthreads();
        if (kt + 1 < 16) {
            loadTile((kt + 1) & 1, kt + 1);
            CP_COMMIT;
        }
        const int s = kt & 1;
        unsigned a[2][4], b[4][2];
#pragma unroll
        for (int mt = 0; mt < 2; ++mt) {
            int r = wm + mt * 16 + g;
            a[mt][0] = *(const unsigned*)&Asb[(s * 128 + r) * 24 + tig * 2];
            a[mt][1] = *(const unsigned*)&Asb[(s * 128 + r + 8) * 24 + tig * 2];
            a[mt][2] = *(const unsigned*)&Asb[(s * 128 + r) * 24 + tig * 2 + 8];
            a[mt][3] = *(const unsigned*)&Asb[(s * 128 + r + 8) * 24 + tig * 2 + 8];
        }
#pragma unroll
        for (int nt = 0; nt < 4; ++nt) {
            int n = wn + nt * 8 + g;
            b[nt][0] = *(const unsigned*)&Bsb[(s * 64 + n) * 24 + tig * 2];
            b[nt][1] = *(const unsigned*)&Bsb[(s * 64 + n) * 24 + tig * 2 + 8];
        }
#pragma unroll
        for (int mt = 0; mt < 2; ++mt)
#pragma unroll
            for (int nt = 0; nt < 4; ++nt) mma16(acc[mt][nt], a[mt], b[nt]);
    }
    __syncthreads();

#pragma unroll
    for (int mt = 0; mt < 2; ++mt) {
#pragma unroll
        for (int nt = 0; nt < 4; ++nt) {
            int r = wm + mt * 16 + g;
            int col = wn + nt * 8 + 2 * tig;
            float c0 = g_cb[col], c1 = g_cb[col + 1];
            ys[r * 68 + col]           = acc[mt][nt][0] + c0;
            ys[r * 68 + col + 1]       = acc[mt][nt][1] + c1;
            ys[(r + 8) * 68 + col]     = acc[mt][nt][2] + c0;
            ys[(r + 8) * 68 + col + 1] = acc[mt][nt][3] + c1;
        }
    }
    for (int idx = tid; idx < 2048; idx += 256)
        Wh1S[(idx >> 6) * 68 + (idx & 63)] = Wh1[idx];
    for (int idx = tid; idx < 704; idx += 256)
        WrS[(idx / 11) * 12 + (idx % 11)] = Wr[idx];
    for (int idx = tid; idx < 1408; idx += 256) {
        int r = idx / 11, j = idx % 11;
        int col = (j < 5) ? j : (17 + j);
        rootS[r * 12 + j] = obs[(size_t)(row0 + r) * 376 + col];
    }
    __syncthreads();

    const float gm0 = gamma[lane], gm1 = gamma[lane + 32];
    const float bt0 = beta[lane],  bt1 = beta[lane + 32];
    const float br0 = br[lane],    br1 = br[lane + 32];
    const float bh1v = bh1[lane], wh2v = Wh2[lane], bh2v = bh2[0];

#pragma unroll 2
    for (int rr = 0; rr < 16; ++rr) {
        const int r = w * 16 + rr;
        const size_t row = (size_t)row0 + r;
        float e0 = br0, e1 = br1;
#pragma unroll
        for (int j = 0; j < 11; ++j) {
            float rv = rootS[r * 12 + j];
            e0 = fmaf(rv, WrS[lane * 12 + j], e0);
            e1 = fmaf(rv, WrS[(lane + 32) * 12 + j], e1);
        }
        float x0 = ys[r * 68 + lane] + e0;
        float x1 = ys[r * 68 + lane + 32] + e1;
        float ssum = x0 + x1;
#pragma unroll
        for (int o = 16; o > 0; o >>= 1) ssum += __shfl_xor_sync(0xffffffffu, ssum, o);
        float mu = ssum * (1.f / 64.f);
        float d0 = x0 - mu, d1 = x1 - mu;
        float vs = d0 * d0 + d1 * d1;
#pragma unroll
        for (int o = 16; o > 0; o >>= 1) vs += __shfl_xor_sync(0xffffffffu, vs, o);
        float inv = rsqrtf(vs * (1.f / 64.f) + 1e-5f);
        float c0 = fmaf(gm0, d0 * inv, bt0);
        float c1 = fmaf(gm1, d1 * inv, bt1);
        out_ctx[row * 64 + lane] = c0;
        out_ctx[row * 64 + lane + 32] = c1;
        ys[r * 68 + lane] = c0;
        ys[r * 68 + lane + 32] = c1;
        __syncwarp();
        float4 hv = {0.f, 0.f, 0.f, 0.f};
#pragma unroll
        for (int d4 = 0; d4 < 16; ++d4) {
            float4 yv = *(const float4*)&ys[r * 68 + 4 * d4];
            float4 wv = *(const float4*)&Wh1S[lane * 68 + 4 * d4];
            hv.x = fmaf(yv.x, wv.x, hv.x);
            hv.y = fmaf(yv.y, wv.y, hv.y);
            hv.z = fmaf(yv.z, wv.z, hv.z);
            hv.w = fmaf(yv.w, wv.w, hv.w);
        }
        float v = fmaxf(hv.x + hv.y + hv.z + hv.w + bh1v, 0.f) * wh2v;
#pragma unroll
        for (int o = 16; o > 0; o >>= 1) v += __shfl_xor_sync(0xffffffffu, v, o);
        if (lane == 0) g_raw[row] = v + bh2v;
        __syncwarp();
    }
}

// ================= batch reductions =================
__global__ void k_reduce_raw() {
    __shared__ float s[256];
    int tid = threadIdx.x;
    int i = blockIdx.x * 512 + tid;
    s[tid] = g_raw[i] + g_raw[i + 256];
    __syncthreads();
    for (int o = 128; o > 0; o >>= 1) {
        if (tid < o) s[tid] += s[tid + o];
        __syncthreads();
    }
    if (tid == 0) g_part[blockIdx.x] = s[0];
}
__global__ void k_finish_raw() {
    __shared__ float s[256];
    int tid = threadIdx.x;
    s[tid] = g_part[tid];
    __syncthreads();
    for (int o = 128; o > 0; o >>= 1) {
        if (tid < o) s[tid] += s[tid + o];
        __syncthreads();
    }
    if (tid == 0) g_scalars[0] = s[0] * (1.f / (float)BATCH);
}
__global__ void k_reduce_lw() {
    __shared__ float s[256];
    int tid = threadIdx.x;
    float mean = g_scalars[0];
    int i = blockIdx.x * 512 + tid;
    s[tid] = expf(0.5f * tanhf(g_raw[i] - mean)) +
             expf(0.5f * tanhf(g_raw[i + 256] - mean));
    __syncthreads();
    for (int o = 128; o > 0; o >>= 1) {
        if (tid < o) s[tid] += s[tid + o];
        __syncthreads();
    }
    if (tid == 0) g_part[blockIdx.x] = s[0];
}
__global__ void k_finish_lw() {
    __shared__ float s[256];
    int tid = threadIdx.x;
    s[tid] = g_part[tid];
    __syncthreads();
    for (int o = 128; o > 0; o >>= 1) {
        if (tid < o) s[tid] += s[tid + o];
        __syncthreads();
    }
    if (tid == 0) g_scalars[1] = fmaxf(s[0] * (1.f / (float)BATCH), 1e-6f);
}
__global__ void k_write_lw(float* __restrict__ out_lw) {
    int i = blockIdx.x * 256 + threadIdx.x;
    float lw = expf(0.5f * tanhf(g_raw[i] - g_scalars[0]));
    out_lw[i] = lw / g_scalars[1];
}

// =====================================================================
extern "C" void kernel_launch(void* const* d_in, const int* in_sizes, int n_in,
                              void* d_out, int out_size) {
    const float* obs   = (const float*)d_in[0];
    const float* W1    = (const float*)d_in[1];
    const float* b1    = (const float*)d_in[2];
    const float* W2    = (const float*)d_in[3];
    const float* b2    = (const float*)d_in[4];
    const float* Wr    = (const float*)d_in[5];
    const float* br    = (const float*)d_in[6];
    const float* Win   = (const float*)d_in[7];
    const float* bin_  = (const float*)d_in[8];
    const float* Wout  = (const float*)d_in[9];
    const float* bout  = (const float*)d_in[10];
    const float* gamma = (const float*)d_in[11];
    const float* beta  = (const float*)d_in[12];
    const float* Wh1   = (const float*)d_in[13];
    const float* bh1   = (const float*)d_in[14];
    const float* Wh2   = (const float*)d_in[15];
    const float* bh2   = (const float*)d_in[16];

    float* out     = (float*)d_out;
    float* out_ctx = out;
    float* out_lw  = out + (size_t)BATCH * 64;
    float* out_ent = out_lw + BATCH;

    cudaFuncSetAttribute(k3a_attn, cudaFuncAttributeMaxDynamicSharedMemorySize,
                         K3A_SMEM_BYTES);
    cudaFuncSetAttribute(k4_out_ln_head, cudaFuncAttributeMaxDynamicSharedMemorySize,
                         K4_SMEM_BYTES);

    k0_fold<<<8, 256>>>(Wr, br, Win, bin_, Wout, bout, W2);
    k1_gemm<<<dim3(BATCH / 128, 2), 256>>>(obs, W1, b1);
    k2_gemm<<<dim3(BATCH / 128, 4), 256>>>(b2);
    k3a_attn<<<BATCH / 16, 256, K3A_SMEM_BYTES>>>(obs, out_ent);
    k4_out_ln_head<<<BATCH / 128, 256, K4_SMEM_BYTES>>>(
        obs, Wr, br, gamma, beta, Wh1, bh1, Wh2, bh2, out_ctx);
    k_reduce_raw<<<256, 256>>>();
    k_finish_raw<<<1, 256>>>();
    k_reduce_lw<<<256, 256>>>();
    k_finish_lw<<<1, 256>>>();
    k_write_lw<<<BATCH / 256, 256>>>(out_lw);
}